// round 11
// baseline (speedup 1.0000x reference)
#include <cuda_runtime.h>
#include <math.h>
#include <stdint.h>

static inline int cdiv(int a, int b){ return (a + b - 1) / b; }

constexpr int kB = 64, kT = 256, kC = 53, kH = 64, kA = 128;
constexpr int kC2 = kC * kC;
constexpr int kN1 = kC2 / 2;
constexpr int kN2 = kC2 / 4;
constexpr int kM  = kB * kT;
constexpr int kKP0 = 2816, kNP1 = 1408, kNP2 = 768;

__device__ float g_u[192], g_v[192];
__device__ float4 g_wq0[4096], g_wq1[8192], g_wq2[8192];
__device__ float4 g_wk0[4096], g_wk1[8192], g_wk2[8192];
__device__ float4 g_whf[6144];                 // w_hh frags: N=192 (NW=6), K=64
__device__ float g_mixp[(size_t)kM * kKP0];
__device__ float g_w0p[(size_t)kNP1 * kKP0];
__device__ float g_w1p[(size_t)kNP2 * kNP1];
__device__ float g_z1[(size_t)kM * kNP1];
__device__ float g_z2[(size_t)kM * kNP2];
__device__ float g_zbar[kB * kN2];

__device__ __forceinline__ float fast_sigmoid(float x){
    float e; asm("ex2.approx.f32 %0, %1;" : "=f"(e) : "f"(-x * 1.4426950408889634f));
    float r; asm("rcp.approx.f32 %0, %1;" : "=f"(r) : "f"(1.f + e));
    return r;
}
__device__ __forceinline__ float fast_tanh(float x){ return fmaf(2.f, fast_sigmoid(2.f * x), -1.f); }
__device__ __forceinline__ uint32_t cvt_tf32(float x){
    uint32_t y; asm("cvt.rna.tf32.f32 %0, %1;" : "=r"(y) : "f"(x)); return y;
}
__device__ __forceinline__ float2 split_tf32(float v){
    float hi = __uint_as_float(cvt_tf32(v));
    float lo = __uint_as_float(cvt_tf32(v - hi));
    return make_float2(hi, lo);
}
__device__ __forceinline__ void st_peer(float* p, float v, uint32_t peer){
    uint32_t l = (uint32_t)__cvta_generic_to_shared(p);
    uint32_t r; asm("mapa.shared::cluster.u32 %0, %1, %2;" : "=r"(r) : "r"(l), "r"(peer));
    asm volatile("st.shared::cluster.f32 [%0], %1;" :: "r"(r), "f"(v) : "memory");
}
__device__ __forceinline__ void cluster_sync_(){
    asm volatile("barrier.cluster.arrive.aligned;" ::: "memory");
    asm volatile("barrier.cluster.wait.aligned;" ::: "memory");
}
__device__ __forceinline__ void cp_async16(void* smem, const void* gmem){
    uint32_t s = (uint32_t)__cvta_generic_to_shared(smem);
    asm volatile("cp.async.cg.shared.global [%0], [%1], 16;" :: "r"(s), "l"(gmem) : "memory");
}
__device__ __forceinline__ void mma_tf32(float* c, const uint32_t* a, const uint32_t* b){
    asm volatile("mma.sync.aligned.m16n8k8.row.col.f32.tf32.tf32.f32 "
        "{%0,%1,%2,%3}, {%4,%5,%6,%7}, {%8,%9}, {%0,%1,%2,%3};"
        : "+f"(c[0]), "+f"(c[1]), "+f"(c[2]), "+f"(c[3])
        : "r"(a[0]), "r"(a[1]), "r"(a[2]), "r"(a[3]), "r"(b[0]), "r"(b[1]));
}

__global__ void prep_small(const float* __restrict__ w_ih, const float* __restrict__ w_emb,
                           const float* __restrict__ b_emb, const float* __restrict__ b_ih)
{
    int gt = blockIdx.x * blockDim.x + threadIdx.x;
    int gs = gridDim.x * blockDim.x;
    for (int j = gt; j < 192; j += gs){
        float su = 0.f, sv = 0.f;
        for (int e = 0; e < 64; e++){
            su += w_ih[j * 64 + e] * w_emb[e];
            sv += w_ih[j * 64 + e] * b_emb[e];
        }
        g_u[j] = su; g_v[j] = sv + b_ih[j];
    }
}

// bake W (N x K row-major) into mma B-fragment order with NW n-warps
__device__ __forceinline__ void bake_one(float4* dst, const float* W, int K, int NW, int idx){
    int kc = idx / (NW * 256), rem = idx % (NW * 256);
    int wn = rem >> 8, r2 = rem & 255;
    int grp = r2 >> 5, lane = r2 & 31;
    int ks = grp >> 2, nt = grp & 3;
    int n = wn * 32 + nt * 8 + (lane >> 2);
    int k = kc * 16 + ks * 8 + (lane & 3);
    float v0 = W[n * K + k], v1 = W[n * K + k + 4];
    float h0 = __uint_as_float(cvt_tf32(v0));
    float h1 = __uint_as_float(cvt_tf32(v1));
    dst[idx] = make_float4(h0, __uint_as_float(cvt_tf32(v0 - h0)),
                           h1, __uint_as_float(cvt_tf32(v1 - h1)));
}

__global__ void prep_frag(const float* __restrict__ qw0, const float* __restrict__ qw1, const float* __restrict__ qw2,
                          const float* __restrict__ kw0, const float* __restrict__ kw1, const float* __restrict__ kw2,
                          const float* __restrict__ w_hh)
{
    int gt = blockIdx.x * blockDim.x + threadIdx.x;
    int gs = gridDim.x * blockDim.x;
    for (int i = gt; i < 4096; i += gs){ bake_one(g_wq0, qw0, 64, 4, i); bake_one(g_wk0, kw0, 64, 4, i); }
    for (int i = gt; i < 8192; i += gs){
        bake_one(g_wq1, qw1, 128, 4, i); bake_one(g_wq2, qw2, 128, 4, i);
        bake_one(g_wk1, kw1, 128, 4, i); bake_one(g_wk2, kw2, 128, 4, i);
    }
    for (int i = gt; i < 6144; i += gs) bake_one(g_whf, w_hh, 64, 6, i);
}

__global__ void pack_clf(const float* __restrict__ clf_w0, const float* __restrict__ clf_w1)
{
    size_t gt = (size_t)blockIdx.x * blockDim.x + threadIdx.x;
    size_t gs = (size_t)gridDim.x * blockDim.x;
    for (size_t idx = gt; idx < (size_t)kNP1 * kKP0; idx += gs){
        int j = (int)(idx / kKP0), k = (int)(idx - (size_t)j * kKP0);
        float v = (j < kN1 && k < kC2) ? clf_w0[(size_t)j * kC2 + k] : 0.f;
        g_w0p[idx] = __uint_as_float(cvt_tf32(v));
    }
    for (size_t idx = gt; idx < (size_t)kNP2 * kNP1; idx += gs){
        int j = (int)(idx / kNP1), k = (int)(idx - (size_t)j * kNP1);
        float v = (j < kN2 && k < kN1) ? clf_w1[(size_t)j * kN1 + k] : 0.f;
        g_w1p[idx] = __uint_as_float(cvt_tf32(v));
    }
}

// ---------------- smem layout (floats) ----------------
constexpr int S_H    = 0;                        // 53*64 fp32 h (own rows)
constexpr int S_HGRU = S_H + kC * kH;            // 53*64 fp32 full (peer pushed)
constexpr int S_B2   = S_HGRU + kC * kH;         // KT 128*53 full (peer pushed)
constexpr int S_TR   = S_B2 + 128 * 53;          // 53*56
constexpr int S_UV   = S_TR + kC * 56;           // 384
constexpr int S_BHH  = S_UV + 384;               // 192
constexpr int S_PW   = S_BHH + 192;              // 64
constexpr int S_X    = S_PW + 64;                // 56
constexpr int S_RED  = S_X + 56;                 // 16
constexpr int S_BIAS = S_RED + 16;               // 6*128
constexpr int S_HG2  = S_BIAS + 768;             // 32*68 float2 (h/hgru split)
constexpr int S_KA   = S_HG2 + 4352;             // buf A; GH(32*196) and QF(32*132) alias
constexpr int S_KB   = S_KA + 8448;
constexpr int S_QA   = S_KB + 8448;
constexpr int S_QB   = S_QA + 8448;
constexpr int SM_FLOATS = S_QB + 8448;
constexpr int SM_BYTES  = SM_FLOATS * 4;         // 224,640 B

// 8-warp tensor-core MLP (R8 geometry): warp_m = wid&1 (16 rows), warp_n = wid>>1 (32 cols).
// OUTMODE 0: relu+split->float2 stride Sout; 1: fp32 stride132; 2: KT[n*53+c]+peer
template<int K, int OUTMODE>
__device__ __forceinline__ void mma_mlp(float* __restrict__ sm, int inOff, int Sin, int outOff, int Sout,
                                        const float4* __restrict__ gw, int biasOff,
                                        int wid, int lane, int c_lo, int c_n, uint32_t peer)
{
    const int warp_m = wid & 1, warp_n = wid >> 1;
    const int g = lane >> 2, l4 = lane & 3;
    constexpr int NC = K / 16;
    const float2* in2 = (const float2*)(sm + inOff);

    float acc[4][4];
#pragma unroll
    for (int i = 0; i < 4; i++)
#pragma unroll
        for (int j = 0; j < 4; j++) acc[i][j] = 0.f;

    float4 bb[2][8];
#pragma unroll
    for (int i = 0; i < 8; i++) bb[0][i] = gw[warp_n * 256 + i * 32 + lane];

    const int r0 = warp_m * 16 + g;
#pragma unroll 2
    for (int kc = 0; kc < NC; kc++){
        const int cur = kc & 1;
        if (kc + 1 < NC){
#pragma unroll
            for (int i = 0; i < 8; i++)
                bb[cur ^ 1][i] = gw[((kc + 1) * 4 + warp_n) * 256 + i * 32 + lane];
        }
#pragma unroll
        for (int ks = 0; ks < 2; ks++){
            const int kk = kc * 16 + ks * 8 + l4;
            float2 a0 = in2[r0 * Sin + kk];
            float2 a1 = in2[(r0 + 8) * Sin + kk];
            float2 a2 = in2[r0 * Sin + kk + 4];
            float2 a3 = in2[(r0 + 8) * Sin + kk + 4];
            uint32_t ahi[4] = {__float_as_uint(a0.x), __float_as_uint(a1.x), __float_as_uint(a2.x), __float_as_uint(a3.x)};
            uint32_t alo[4] = {__float_as_uint(a0.y), __float_as_uint(a1.y), __float_as_uint(a2.y), __float_as_uint(a3.y)};
#pragma unroll
            for (int nt = 0; nt < 4; nt++){
                float4 w = bb[cur][ks * 4 + nt];
                uint32_t bhi[2] = {__float_as_uint(w.x), __float_as_uint(w.z)};
                uint32_t blo[2] = {__float_as_uint(w.y), __float_as_uint(w.w)};
                mma_tf32(acc[nt], ahi, bhi);
                mma_tf32(acc[nt], ahi, blo);
                mma_tf32(acc[nt], alo, bhi);
            }
        }
    }

    const float* sbias = sm + biasOff;
    const int row0 = r0, row1 = r0 + 8;
    const bool ok0 = row0 < c_n, ok1 = row1 < c_n;
#pragma unroll
    for (int nt = 0; nt < 4; nt++){
        const int n0 = warp_n * 32 + nt * 8 + 2 * l4;
        const float b0 = sbias[n0], b1 = sbias[n0 + 1];
        float v00 = acc[nt][0] + b0, v01 = acc[nt][1] + b1;
        float v10 = acc[nt][2] + b0, v11 = acc[nt][3] + b1;
        if (OUTMODE == 0){
            v00 = fmaxf(v00, 0.f); v01 = fmaxf(v01, 0.f);
            v10 = fmaxf(v10, 0.f); v11 = fmaxf(v11, 0.f);
            float2* o2 = (float2*)(sm + outOff);
            if (ok0){ o2[row0 * Sout + n0] = split_tf32(v00); o2[row0 * Sout + n0 + 1] = split_tf32(v01); }
            if (ok1){ o2[row1 * Sout + n0] = split_tf32(v10); o2[row1 * Sout + n0 + 1] = split_tf32(v11); }
        } else if (OUTMODE == 1){
            float* oq = sm + outOff;
            if (ok0){ oq[row0 * 132 + n0] = v00; oq[row0 * 132 + n0 + 1] = v01; }
            if (ok1){ oq[row1 * 132 + n0] = v10; oq[row1 * 132 + n0 + 1] = v11; }
        } else {
            float* kt = sm + outOff;
            if (ok0){
                int c = c_lo + row0;
                kt[n0 * 53 + c] = v00;       st_peer(&kt[n0 * 53 + c], v00, peer);
                kt[(n0 + 1) * 53 + c] = v01; st_peer(&kt[(n0 + 1) * 53 + c], v01, peer);
            }
            if (ok1){
                int c = c_lo + row1;
                kt[n0 * 53 + c] = v10;       st_peer(&kt[n0 * 53 + c], v10, peer);
                kt[(n0 + 1) * 53 + c] = v11; st_peer(&kt[(n0 + 1) * 53 + c], v11, peer);
            }
        }
    }
}

// 6-warp N=192 GRU matmul: gh = h @ w_hh^T + b_hh, out fp32 stride 196 (2 m-tiles/warp)
__device__ __forceinline__ void mma_gru(float* __restrict__ sm, const float4* __restrict__ gw,
                                        int wn, int lane)
{
    const int g = lane >> 2, l4 = lane & 3;
    const float2* in2 = (const float2*)(sm + S_HG2);

    float acc[2][4][4];
#pragma unroll
    for (int m = 0; m < 2; m++)
#pragma unroll
        for (int i = 0; i < 4; i++)
#pragma unroll
            for (int j = 0; j < 4; j++) acc[m][i][j] = 0.f;

    float4 bb[2][8];
#pragma unroll
    for (int i = 0; i < 8; i++) bb[0][i] = gw[wn * 256 + i * 32 + lane];

#pragma unroll
    for (int kc = 0; kc < 4; kc++){
        const int cur = kc & 1;
        if (kc + 1 < 4){
#pragma unroll
            for (int i = 0; i < 8; i++)
                bb[cur ^ 1][i] = gw[((kc + 1) * 6 + wn) * 256 + i * 32 + lane];
        }
#pragma unroll
        for (int ks = 0; ks < 2; ks++){
            const int kk = kc * 16 + ks * 8 + l4;
            uint32_t ahi[2][4], alo[2][4];
#pragma unroll
            for (int mt = 0; mt < 2; mt++){
                const int r0 = mt * 16 + g;
                float2 a0 = in2[r0 * 68 + kk];
                float2 a1 = in2[(r0 + 8) * 68 + kk];
                float2 a2 = in2[r0 * 68 + kk + 4];
                float2 a3 = in2[(r0 + 8) * 68 + kk + 4];
                ahi[mt][0] = __float_as_uint(a0.x); ahi[mt][1] = __float_as_uint(a1.x);
                ahi[mt][2] = __float_as_uint(a2.x); ahi[mt][3] = __float_as_uint(a3.x);
                alo[mt][0] = __float_as_uint(a0.y); alo[mt][1] = __float_as_uint(a1.y);
                alo[mt][2] = __float_as_uint(a2.y); alo[mt][3] = __float_as_uint(a3.y);
            }
#pragma unroll
            for (int nt = 0; nt < 4; nt++){
                float4 w = bb[cur][ks * 4 + nt];
                uint32_t bhi[2] = {__float_as_uint(w.x), __float_as_uint(w.z)};
                uint32_t blo[2] = {__float_as_uint(w.y), __float_as_uint(w.w)};
#pragma unroll
                for (int mt = 0; mt < 2; mt++){
                    mma_tf32(acc[mt][nt], ahi[mt], bhi);
                    mma_tf32(acc[mt][nt], ahi[mt], blo);
                    mma_tf32(acc[mt][nt], alo[mt], bhi);
                }
            }
        }
    }

    float* gh = sm + S_KA;
    const float* sbias = sm + S_BHH;
#pragma unroll
    for (int mt = 0; mt < 2; mt++){
        const int row0 = mt * 16 + g, row1 = row0 + 8;
#pragma unroll
        for (int nt = 0; nt < 4; nt++){
            const int n0 = wn * 32 + nt * 8 + 2 * l4;
            const float b0 = sbias[n0], b1 = sbias[n0 + 1];
            gh[row0 * 196 + n0] = acc[mt][nt][0] + b0; gh[row0 * 196 + n0 + 1] = acc[mt][nt][1] + b1;
            gh[row1 * 196 + n0] = acc[mt][nt][2] + b0; gh[row1 * 196 + n0 + 1] = acc[mt][nt][3] + b1;
        }
    }
}

__global__ void __cluster_dims__(2, 1, 1) __launch_bounds__(256, 1)
recurrent_kernel(const float* __restrict__ x,
                 const float* __restrict__ b_hh,
                 const float* __restrict__ qb0, const float* __restrict__ qb1, const float* __restrict__ qb2,
                 const float* __restrict__ kb0, const float* __restrict__ kb1, const float* __restrict__ kb2,
                 const float* __restrict__ gate_bias,
                 const float* __restrict__ pred_w, const float* __restrict__ pred_b,
                 float* __restrict__ out_mix, float* __restrict__ out_fnc, float* __restrict__ out_pred)
{
    extern __shared__ float sm[];
    const int tid = threadIdx.x;
    const int b = blockIdx.x >> 1;
    const uint32_t rank = blockIdx.x & 1;
    const uint32_t peer = rank ^ 1;
    const int c_lo = rank ? 27 : 0;
    const int c_n  = rank ? 26 : 27;

    for (int i = tid; i < kC * kH; i += 256) sm[S_H + i] = 0.f;
    for (int i = tid; i < SM_FLOATS - S_HG2; i += 256) sm[S_HG2 + i] = 0.f;
    if (tid < 192){ sm[S_UV + tid] = g_u[tid]; sm[S_UV + 192 + tid] = g_v[tid]; sm[S_BHH + tid] = b_hh[tid]; }
    if (tid < 64) sm[S_PW + tid] = pred_w[tid];
    if (tid < 128){
        sm[S_BIAS + tid]       = kb0[tid];
        sm[S_BIAS + 128 + tid] = kb1[tid];
        sm[S_BIAS + 256 + tid] = kb2[tid];
        sm[S_BIAS + 384 + tid] = qb0[tid];
        sm[S_BIAS + 512 + tid] = qb1[tid];
        sm[S_BIAS + 640 + tid] = qb2[tid];
    }
    const float predb = pred_b[0];
    __syncthreads();

    const int hh = tid & 63, cg = tid >> 6;
    const int lane = tid & 31, wid = tid >> 5;
    const int nloc = c_n * 53;
    const int nge = c_n * 64;

    float facc[6], gbr[6];
#pragma unroll
    for (int j = 0; j < 6; j++){
        facc[j] = 0.f;
        int idx = tid + j * 256;
        gbr[j] = (idx < nloc) ? gate_bias[c_lo * 53 + idx] : 0.f;
    }

    float xr = (tid < kC) ? x[((size_t)b * kT) * kC + tid] : 0.f;

    cluster_sync_();

    for (int t = 0; t < kT; t++){
        if (tid < kC) sm[S_X + tid] = xr;
        __syncthreads();
        {
            int tn = (t + 1 < kT) ? t + 1 : t;
            if (tid < kC) xr = x[((size_t)b * kT + tn) * kC + tid];
        }

        // ---- Stage A1: gh via tensor cores (6 warps) ----
        if (wid < 6) mma_gru(sm, g_whf, wid, lane);
        __syncthreads();

        // ---- Stage A2: GRU fuse; write hgru fp32 (own+peer) + split ----
        {
            const float* GH = sm + S_KA;
            float2* hg2 = (float2*)(sm + S_HG2);
#pragma unroll
            for (int j = 0; j < 7; j++){
                int idx = tid + j * 256;
                if (idx < nge){
                    int cl = idx >> 6, h2 = idx & 63;
                    int c = c_lo + cl;
                    float xi = sm[S_X + c];
                    float r = fast_sigmoid(fmaf(xi, sm[S_UV + h2],       sm[S_UV + 192 + h2]) + GH[cl * 196 + h2]);
                    float z = fast_sigmoid(fmaf(xi, sm[S_UV + 64 + h2],  sm[S_UV + 256 + h2]) + GH[cl * 196 + 64 + h2]);
                    float n = fast_tanh(   fmaf(xi, sm[S_UV + 128 + h2], sm[S_UV + 320 + h2]) + r * GH[cl * 196 + 128 + h2]);
                    float hg = (1.f - z) * n + z * sm[S_H + c * 64 + h2];
                    sm[S_HGRU + c * 64 + h2] = hg;
                    st_peer(&sm[S_HGRU + c * 64 + h2], hg, peer);
                    hg2[cl * 68 + h2] = split_tf32(hg);
                }
            }
        }
        __syncthreads();

        // ---- Stage B: sequential 6 layers, all 8 warps per GEMM (R8 structure) ----
        mma_mlp<64,  0>(sm, S_HG2, 68,  S_KA, 132, g_wk0, S_BIAS,       wid, lane, c_lo, c_n, peer); __syncthreads();
        mma_mlp<128, 0>(sm, S_KA, 132, S_KB, 132, g_wk1, S_BIAS + 128, wid, lane, c_lo, c_n, peer); __syncthreads();
        mma_mlp<128, 2>(sm, S_KB, 132, S_B2, 0,   g_wk2, S_BIAS + 256, wid, lane, c_lo, c_n, peer); __syncthreads();
        mma_mlp<64,  0>(sm, S_HG2, 68,  S_QA, 132, g_wq0, S_BIAS + 384, wid, lane, c_lo, c_n, peer); __syncthreads();
        mma_mlp<128, 0>(sm, S_QA, 132, S_QB, 132, g_wq1, S_BIAS + 512, wid, lane, c_lo, c_n, peer); __syncthreads();
        mma_mlp<128, 1>(sm, S_QB, 132, S_KA, 0,   g_wq2, S_BIAS + 640, wid, lane, c_lo, c_n, peer);

        cluster_sync_();   // full KT + full hgru visible

        // ---- Stage C: transfer = q(QF at S_KA) @ KT ----
        {
            const int j = hh;
            if (j < kC){
                float acc[7];
#pragma unroll
                for (int i = 0; i < 7; i++) acc[i] = 0.f;
#pragma unroll 1
                for (int k = 0; k < 128; k += 4){
                    const float kv0 = sm[S_B2 + (k + 0) * 53 + j];
                    const float kv1 = sm[S_B2 + (k + 1) * 53 + j];
                    const float kv2 = sm[S_B2 + (k + 2) * 53 + j];
                    const float kv3 = sm[S_B2 + (k + 3) * 53 + j];
#pragma unroll
                    for (int ci = 0; ci < 7; ci++){
                        int cl = cg + 4 * ci;
                        if (cl < c_n){
                            const float4 qv = *(const float4*)&sm[S_KA + cl * 132 + k];
                            acc[ci] = fmaf(qv.x, kv0, fmaf(qv.y, kv1, fmaf(qv.z, kv2, fmaf(qv.w, kv3, acc[ci]))));
                        }
                    }
                }
#pragma unroll
                for (int ci = 0; ci < 7; ci++){
                    int cl = cg + 4 * ci;
                    if (cl < c_n) sm[S_TR + (c_lo + cl) * 56 + j] = acc[ci];
                }
            }
        }
        __syncthreads();

        // ---- norm ----
        {
            float p = 0.f;
            for (int idx = tid; idx < nloc; idx += 256){
                int cc = c_lo + idx / 53, dd = idx % 53;
                float v = sm[S_TR + cc * 56 + dd];
                p = fmaf(v, v, p);
            }
#pragma unroll
            for (int o = 16; o; o >>= 1) p += __shfl_xor_sync(0xffffffffu, p, o);
            if ((tid & 31) == 0) sm[S_RED + (tid >> 5)] = p;
        }
        __syncthreads();
        if (tid == 0){
            float s = 0.f;
            for (int i = 0; i < 8; i++) s += sm[S_RED + i];
            sm[S_RED + 10] = s;
            st_peer(&sm[S_RED + 11], s, peer);
        }
        cluster_sync_();
        const float inv = rsqrtf(sm[S_RED + 10] + sm[S_RED + 11]);

        // ---- normalize + gate + emit mix + reg-FNC ----
        {
            float* mix_bt = out_mix + ((size_t)b * kT + t) * kC2;
            float* mixp_bt = g_mixp + ((size_t)b * kT + t) * kKP0;
#pragma unroll
            for (int j = 0; j < 6; j++){
                int idx = tid + j * 256;
                if (idx < nloc){
                    int glob = c_lo * 53 + idx;
                    int cc = c_lo + idx / 53, dd = idx % 53;
                    float v = sm[S_TR + cc * 56 + dd] * inv;
                    float gate = fast_sigmoid(fabsf(v) + gbr[j]);
                    float val = v * gate;
                    sm[S_TR + cc * 56 + dd] = val;
                    mix_bt[glob] = val;
                    mixp_bt[glob] = __uint_as_float(cvt_tf32(val));
                    facc[j] += val;
                }
            }
        }
        __syncthreads();

        // ---- Stage D: h_new = transfer(own) @ hgru(full); write h fp32 + split ----
        {
            float acc[7];
#pragma unroll
            for (int i = 0; i < 7; i++) acc[i] = 0.f;
#pragma unroll 1
            for (int d = 0; d < 52; d += 4){
                float g0 = sm[S_HGRU + (d + 0) * 64 + hh];
                float g1 = sm[S_HGRU + (d + 1) * 64 + hh];
                float g2 = sm[S_HGRU + (d + 2) * 64 + hh];
                float g3 = sm[S_HGRU + (d + 3) * 64 + hh];
#pragma unroll
                for (int ci = 0; ci < 7; ci++){
                    int cl = cg + 4 * ci;
                    if (cl < c_n){
                        const float4 tv = *(const float4*)&sm[S_TR + (c_lo + cl) * 56 + d];
                        acc[ci] += tv.x * g0 + tv.y * g1 + tv.z * g2 + tv.w * g3;
                    }
                }
            }
            {
                float g = sm[S_HGRU + 52 * 64 + hh];
#pragma unroll
                for (int ci = 0; ci < 7; ci++){
                    int cl = cg + 4 * ci;
                    if (cl < c_n) acc[ci] += sm[S_TR + (c_lo + cl) * 56 + 52] * g;
                }
            }
            float2* hg2 = (float2*)(sm + S_HG2);
#pragma unroll
            for (int ci = 0; ci < 7; ci++){
                int cl = cg + 4 * ci;
                if (cl < c_n){
                    sm[S_H + (c_lo + cl) * 64 + hh] = acc[ci];
                    hg2[cl * 68 + hh] = split_tf32(acc[ci]);
                }
            }
        }
        __syncthreads();

        if (t < kT - 1 && tid < c_n){
            int c = c_lo + tid;
            float s2 = 0.f;
#pragma unroll
            for (int k = 0; k < 64; k += 4){
                const float4 hv = *(const float4*)&sm[S_H + c * 64 + k];
                s2 += hv.x * sm[S_PW + k] + hv.y * sm[S_PW + k + 1] + hv.z * sm[S_PW + k + 2] + hv.w * sm[S_PW + k + 3];
            }
            out_pred[((size_t)b * (kT - 1) + t) * kC + c] = s2 + predb;
        }

        cluster_sync_();
    }

#pragma unroll
    for (int j = 0; j < 6; j++){
        int idx = tid + j * 256;
        if (idx < nloc)
            out_fnc[(size_t)b * kC2 + c_lo * 53 + idx] = facc[j] * (1.f / 256.f);
    }
}

// ---------------- tf32 tensor-core classifier GEMM ----------------
template<bool RELU, bool CVT>
__global__ __launch_bounds__(256, 2) void mma_gemm(const float* __restrict__ A, const float* __restrict__ B,
                                                   const float* __restrict__ bias, float* __restrict__ C,
                                                   int M, int Nstore, int Nreal, int K)
{
    extern __shared__ float smg[];
    float* As = smg;
    float* Bs = smg + 2 * 4608;

    const int tid = threadIdx.x;
    const int wid = tid >> 5, lane = tid & 31;
    const int warp_m = wid & 3, warp_n = wid >> 2;
    const int g = lane >> 2, l4 = lane & 3;
    const int bm = blockIdx.y * 128, bn = blockIdx.x * 128;

    const float* Ab = A + (size_t)bm * K;
    const float* Bb = B + (size_t)bn * K;

    float acc[2][8][4];
#pragma unroll
    for (int i = 0; i < 2; i++)
#pragma unroll
        for (int j = 0; j < 8; j++)
#pragma unroll
            for (int q = 0; q < 4; q++) acc[i][j][q] = 0.f;

    const int nk = K >> 5;

    auto load_tile = [&](int kt, int buf){
        const int k0 = kt * 32;
        float* as = As + buf * 4608;
        float* bs = Bs + buf * 4608;
#pragma unroll
        for (int i = 0; i < 4; i++){
            int ch = tid + i * 256;
            int row = ch >> 3;
            int ko = (ch & 7) * 4;
            cp_async16(&as[row * 36 + ko], Ab + (size_t)row * K + k0 + ko);
            cp_async16(&bs[row * 36 + ko], Bb + (size_t)row * K + k0 + ko);
        }
        asm volatile("cp.async.commit_group;" ::: "memory");
    };

    load_tile(0, 0);

    for (int kt = 0; kt < nk; kt++){
        const int buf = kt & 1;
        if (kt + 1 < nk){
            load_tile(kt + 1, buf ^ 1);
            asm volatile("cp.async.wait_group 1;" ::: "memory");
        } else {
            asm volatile("cp.async.wait_group 0;" ::: "memory");
        }
        __syncthreads();

        const float* as = As + buf * 4608;
        const float* bs = Bs + buf * 4608;
#pragma unroll
        for (int s = 0; s < 4; s++){
            const int kk = s * 8 + l4;
            uint32_t a[2][4], bf[8][2];
            const int r0 = warp_m * 32 + g;
            a[0][0] = __float_as_uint(as[(r0     ) * 36 + kk]);
            a[0][1] = __float_as_uint(as[(r0 +  8) * 36 + kk]);
            a[0][2] = __float_as_uint(as[(r0     ) * 36 + kk + 4]);
            a[0][3] = __float_as_uint(as[(r0 +  8) * 36 + kk + 4]);
            a[1][0] = __float_as_uint(as[(r0 + 16) * 36 + kk]);
            a[1][1] = __float_as_uint(as[(r0 + 24) * 36 + kk]);
            a[1][2] = __float_as_uint(as[(r0 + 16) * 36 + kk + 4]);
            a[1][3] = __float_as_uint(as[(r0 + 24) * 36 + kk + 4]);
#pragma unroll
            for (int nt = 0; nt < 8; nt++){
                const int nb = warp_n * 64 + nt * 8 + g;
                bf[nt][0] = __float_as_uint(bs[nb * 36 + kk]);
                bf[nt][1] = __float_as_uint(bs[nb * 36 + kk + 4]);
            }
#pragma unroll
            for (int mt = 0; mt < 2; mt++)
#pragma unroll
                for (int nt = 0; nt < 8; nt++)
                    mma_tf32(acc[mt][nt], a[mt], bf[nt]);
        }
        __syncthreads();
    }

#pragma unroll
    for (int mt = 0; mt < 2; mt++){
#pragma unroll
        for (int nt = 0; nt < 8; nt++){
            const int row = bm + warp_m * 32 + mt * 16 + g;
            const int col = bn + warp_n * 64 + nt * 8 + 2 * l4;
            const float b0v = (col < Nreal) ? bias[col] : 0.f;
            const float b1v = (col + 1 < Nreal) ? bias[col + 1] : 0.f;
            float v00 = acc[mt][nt][0] + b0v;
            float v01 = acc[mt][nt][1] + b1v;
            float v10 = acc[mt][nt][2] + b0v;
            float v11 = acc[mt][nt][3] + b1v;
            if (RELU){
                v00 = fmaxf(v00, 0.f); v01 = fmaxf(v01, 0.f);
                v10 = fmaxf(v10, 0.f); v11 = fmaxf(v11, 0.f);
            }
            if (CVT){
                v00 = __uint_as_float(cvt_tf32(v00)); v01 = __uint_as_float(cvt_tf32(v01));
                v10 = __uint_as_float(cvt_tf32(v10)); v11 = __uint_as_float(cvt_tf32(v11));
            }
            C[(size_t)row * Nstore + col]           = v00;
            C[(size_t)row * Nstore + col + 1]       = v01;
            C[(size_t)(row + 8) * Nstore + col]     = v10;
            C[(size_t)(row + 8) * Nstore + col + 1] = v11;
        }
    }
}

__global__ void zbar_kernel()
{
    const int b = blockIdx.x;
    for (int j = threadIdx.x; j < kN2; j += blockDim.x){
        float s = 0.f;
        for (int t = 0; t < kT; t++) s += g_z2[((size_t)b * kT + t) * kNP2 + j];
        g_zbar[b * kN2 + j] = s * (1.f / (float)kT);
    }
}

__global__ void logits_kernel(const float* __restrict__ w2, const float* __restrict__ b2, float* __restrict__ out)
{
    __shared__ float red[8];
    const int b = blockIdx.x >> 1, o = blockIdx.x & 1;
    float s = 0.f;
    for (int j = threadIdx.x; j < kN2; j += 256)
        s += g_zbar[b * kN2 + j] * w2[o * kN2 + j];
#pragma unroll
    for (int off = 16; off; off >>= 1) s += __shfl_xor_sync(0xffffffffu, s, off);
    if ((threadIdx.x & 31) == 0) red[threadIdx.x >> 5] = s;
    __syncthreads();
    if (threadIdx.x == 0){
        float t = 0.f;
        for (int i = 0; i < 8; i++) t += red[i];
        out[b * 2 + o] = t + b2[o];
    }
}

__global__ void xcopy_kernel(const float* __restrict__ x, float* __restrict__ outx)
{
    const int n = kB * (kT - 1) * kC;
    for (int idx = blockIdx.x * blockDim.x + threadIdx.x; idx < n; idx += gridDim.x * blockDim.x){
        int b = idx / ((kT - 1) * kC);
        int r = idx - b * (kT - 1) * kC;
        outx[idx] = x[(size_t)b * kT * kC + kC + r];
    }
}

extern "C" void kernel_launch(void* const* d_in, const int* in_sizes, int n_in,
                              void* d_out, int out_size)
{
    const float* x        = (const float*)d_in[0];
    const float* w_emb    = (const float*)d_in[1];
    const float* b_emb    = (const float*)d_in[2];
    const float* w_ih     = (const float*)d_in[3];
    const float* w_hh     = (const float*)d_in[4];
    const float* b_ih     = (const float*)d_in[5];
    const float* b_hh     = (const float*)d_in[6];
    const float* q_w0     = (const float*)d_in[7];
    const float* q_b0     = (const float*)d_in[8];
    const float* q_w1     = (const float*)d_in[9];
    const float* q_b1     = (const float*)d_in[10];
    const float* q_w2     = (const float*)d_in[11];
    const float* q_b2     = (const float*)d_in[12];
    const float* k_w0     = (const float*)d_in[13];
    const float* k_b0     = (const float*)d_in[14];
    const float* k_w1     = (const float*)d_in[15];
    const float* k_b1     = (const float*)d_in[16];
    const float* k_w2     = (const float*)d_in[17];
    const float* k_b2     = (const float*)d_in[18];
    const float* gate_bias= (const float*)d_in[19];
    const float* pred_w   = (const float*)d_in[20];
    const float* pred_b   = (const float*)d_in[21];
    const float* clf_w0   = (const float*)d_in[22];
    const float* clf_b0   = (const float*)d_in[23];
    const float* clf_w1   = (const float*)d_in[24];
    const float* clf_b1   = (const float*)d_in[25];
    const float* clf_w2   = (const float*)d_in[26];
    const float* clf_b2   = (const float*)d_in[27];

    float* out      = (float*)d_out;
    float* out_log  = out;
    float* out_fnc  = out + 2 * kB;
    float* out_mix  = out_fnc + (size_t)kB * kC2;
    float* out_pred = out_mix + (size_t)kB * kT * kC2;
    float* out_x    = out_pred + (size_t)kB * (kT - 1) * kC;

    cudaFuncSetAttribute(recurrent_kernel, cudaFuncAttributeMaxDynamicSharedMemorySize, SM_BYTES);
    cudaFuncSetAttribute(mma_gemm<true, true>,  cudaFuncAttributeMaxDynamicSharedMemorySize, 2 * 2 * 4608 * 4);
    cudaFuncSetAttribute(mma_gemm<true, false>, cudaFuncAttributeMaxDynamicSharedMemorySize, 2 * 2 * 4608 * 4);

    prep_small<<<4, 256>>>(w_ih, w_emb, b_emb, b_ih);
    prep_frag<<<40, 256>>>(q_w0, q_w1, q_w2, k_w0, k_w1, k_w2, w_hh);
    pack_clf<<<2048, 256>>>(clf_w0, clf_w1);

    recurrent_kernel<<<2 * kB, 256, SM_BYTES>>>(x, b_hh, q_b0, q_b1, q_b2, k_b0, k_b1, k_b2,
                                                gate_bias, pred_w, pred_b,
                                                out_mix, out_fnc, out_pred);

    float *pz1, *pz2, *pw0p, *pw1p, *pmixp;
    cudaGetSymbolAddress((void**)&pz1,   g_z1);
    cudaGetSymbolAddress((void**)&pz2,   g_z2);
    cudaGetSymbolAddress((void**)&pw0p,  g_w0p);
    cudaGetSymbolAddress((void**)&pw1p,  g_w1p);
    cudaGetSymbolAddress((void**)&pmixp, g_mixp);

    const int smem_gemm = 2 * 2 * 4608 * 4;
    mma_gemm<true, true ><<<dim3(kNP1 / 128, kM / 128), 256, smem_gemm>>>(pmixp, pw0p, clf_b0, pz1, kM, kNP1, kN1, kKP0);
    mma_gemm<true, false><<<dim3(kNP2 / 128, kM / 128), 256, smem_gemm>>>(pz1,   pw1p, clf_b1, pz2, kM, kNP2, kN2, kNP1);

    zbar_kernel<<<kB, 256>>>();
    logits_kernel<<<2 * kB, 256>>>(clf_w2, clf_b2, out_log);
    xcopy_kernel<<<512, 256>>>(x, out_x);
}

// round 12
// speedup vs baseline: 1.0219x; 1.0219x over previous
#include <cuda_runtime.h>
#include <math.h>
#include <stdint.h>

static inline int cdiv(int a, int b){ return (a + b - 1) / b; }

constexpr int kB = 64, kT = 256, kC = 53, kH = 64, kA = 128;
constexpr int kC2 = kC * kC;
constexpr int kN1 = kC2 / 2;
constexpr int kN2 = kC2 / 4;
constexpr int kM  = kB * kT;
constexpr int kKP0 = 2816, kNP1 = 1408, kNP2 = 768;

__device__ float g_u[192], g_v[192];
__device__ float g_whht[64 * 192];
__device__ float4 g_wq0[4096], g_wq1[8192], g_wq2[8192];
__device__ float4 g_wk0[4096], g_wk1[8192], g_wk2[8192];
__device__ float g_mixp[(size_t)kM * kKP0];
__device__ float g_w0p[(size_t)kNP1 * kKP0];
__device__ float g_w1p[(size_t)kNP2 * kNP1];
__device__ float g_z1[(size_t)kM * kNP1];
__device__ float g_z2[(size_t)kM * kNP2];
__device__ float g_zbar[kB * kN2];

__device__ __forceinline__ float fast_sigmoid(float x){
    float e; asm("ex2.approx.f32 %0, %1;" : "=f"(e) : "f"(-x * 1.4426950408889634f));
    float r; asm("rcp.approx.f32 %0, %1;" : "=f"(r) : "f"(1.f + e));
    return r;
}
__device__ __forceinline__ float fast_tanh(float x){ return fmaf(2.f, fast_sigmoid(2.f * x), -1.f); }
__device__ __forceinline__ uint32_t cvt_tf32(float x){
    uint32_t y; asm("cvt.rna.tf32.f32 %0, %1;" : "=r"(y) : "f"(x)); return y;
}
__device__ __forceinline__ float2 split_tf32(float v){
    float hi = __uint_as_float(cvt_tf32(v));
    float lo = __uint_as_float(cvt_tf32(v - hi));
    return make_float2(hi, lo);
}
__device__ __forceinline__ void st_peer2(float2* p, float2 v, uint32_t peer){
    uint32_t l = (uint32_t)__cvta_generic_to_shared(p);
    uint32_t r; asm("mapa.shared::cluster.u32 %0, %1, %2;" : "=r"(r) : "r"(l), "r"(peer));
    long long vv; vv = *(long long*)&v;
    asm volatile("st.shared::cluster.b64 [%0], %1;" :: "r"(r), "l"(vv) : "memory");
}
__device__ __forceinline__ void st_peer(float* p, float v, uint32_t peer){
    uint32_t l = (uint32_t)__cvta_generic_to_shared(p);
    uint32_t r; asm("mapa.shared::cluster.u32 %0, %1, %2;" : "=r"(r) : "r"(l), "r"(peer));
    asm volatile("st.shared::cluster.f32 [%0], %1;" :: "r"(r), "f"(v) : "memory");
}
__device__ __forceinline__ void cluster_sync_(){
    asm volatile("barrier.cluster.arrive.aligned;" ::: "memory");
    asm volatile("barrier.cluster.wait.aligned;" ::: "memory");
}
__device__ __forceinline__ void cp_async16(void* smem, const void* gmem){
    uint32_t s = (uint32_t)__cvta_generic_to_shared(smem);
    asm volatile("cp.async.cg.shared.global [%0], [%1], 16;" :: "r"(s), "l"(gmem) : "memory");
}
__device__ __forceinline__ void mma_tf32(float* c, const uint32_t* a, const uint32_t* b){
    asm volatile("mma.sync.aligned.m16n8k8.row.col.f32.tf32.tf32.f32 "
        "{%0,%1,%2,%3}, {%4,%5,%6,%7}, {%8,%9}, {%0,%1,%2,%3};"
        : "+f"(c[0]), "+f"(c[1]), "+f"(c[2]), "+f"(c[3])
        : "r"(a[0]), "r"(a[1]), "r"(a[2]), "r"(a[3]), "r"(b[0]), "r"(b[1]));
}

__global__ void prep_small(const float* __restrict__ w_ih, const float* __restrict__ w_emb,
                           const float* __restrict__ b_emb, const float* __restrict__ b_ih,
                           const float* __restrict__ w_hh)
{
    int gt = blockIdx.x * blockDim.x + threadIdx.x;
    int gs = gridDim.x * blockDim.x;
    for (int j = gt; j < 192; j += gs){
        float su = 0.f, sv = 0.f;
        for (int e = 0; e < 64; e++){
            su += w_ih[j * 64 + e] * w_emb[e];
            sv += w_ih[j * 64 + e] * b_emb[e];
        }
        g_u[j] = su; g_v[j] = sv + b_ih[j];
    }
    for (int idx = gt; idx < 64 * 192; idx += gs){
        int k = idx / 192, j = idx - k * 192;
        g_whht[idx] = w_hh[j * 64 + k];
    }
}

// bake W (N x K row-major) into mma B-fragment order, NW=4 n-warps
__device__ __forceinline__ void bake_one(float4* dst, const float* W, int K, int idx){
    int kc = idx >> 10, rem = idx & 1023;
    int wn = rem >> 8, r2 = rem & 255;
    int grp = r2 >> 5, lane = r2 & 31;
    int ks = grp >> 2, nt = grp & 3;
    int n = wn * 32 + nt * 8 + (lane >> 2);
    int k = kc * 16 + ks * 8 + (lane & 3);
    float v0 = W[n * K + k], v1 = W[n * K + k + 4];
    float h0 = __uint_as_float(cvt_tf32(v0));
    float h1 = __uint_as_float(cvt_tf32(v1));
    dst[idx] = make_float4(h0, __uint_as_float(cvt_tf32(v0 - h0)),
                           h1, __uint_as_float(cvt_tf32(v1 - h1)));
}

__global__ void prep_frag(const float* __restrict__ qw0, const float* __restrict__ qw1, const float* __restrict__ qw2,
                          const float* __restrict__ kw0, const float* __restrict__ kw1, const float* __restrict__ kw2)
{
    int gt = blockIdx.x * blockDim.x + threadIdx.x;
    int gs = gridDim.x * blockDim.x;
    for (int i = gt; i < 4096; i += gs){ bake_one(g_wq0, qw0, 64, i); bake_one(g_wk0, kw0, 64, i); }
    for (int i = gt; i < 8192; i += gs){
        bake_one(g_wq1, qw1, 128, i); bake_one(g_wq2, qw2, 128, i);
        bake_one(g_wk1, kw1, 128, i); bake_one(g_wk2, kw2, 128, i);
    }
}

__global__ void pack_clf(const float* __restrict__ clf_w0, const float* __restrict__ clf_w1)
{
    size_t gt = (size_t)blockIdx.x * blockDim.x + threadIdx.x;
    size_t gs = (size_t)gridDim.x * blockDim.x;
    for (size_t idx = gt; idx < (size_t)kNP1 * kKP0; idx += gs){
        int j = (int)(idx / kKP0), k = (int)(idx - (size_t)j * kKP0);
        float v = (j < kN1 && k < kC2) ? clf_w0[(size_t)j * kC2 + k] : 0.f;
        g_w0p[idx] = __uint_as_float(cvt_tf32(v));
    }
    for (size_t idx = gt; idx < (size_t)kNP2 * kNP1; idx += gs){
        int j = (int)(idx / kNP1), k = (int)(idx - (size_t)j * kNP1);
        float v = (j < kN2 && k < kN1) ? clf_w1[(size_t)j * kN1 + k] : 0.f;
        g_w1p[idx] = __uint_as_float(cvt_tf32(v));
    }
}

// ---------------- smem layout (floats) ----------------
constexpr int S_H    = 0;                        // 53*64 fp32 h (own rows)
constexpr int S_TR   = S_H + kC * kH;            // 27*56 (own rows, local idx)
constexpr int S_WHH  = S_TR + 27 * 56;           // 64*192
constexpr int S_UV   = S_WHH + 64 * 192;         // 384
constexpr int S_BHH  = S_UV + 384;               // 192
constexpr int S_PW   = S_BHH + 192;              // 64
constexpr int S_X    = S_PW + 64;                // 56
constexpr int S_RED  = S_X + 56;                 // 16
constexpr int S_BIAS = S_RED + 16;               // 6*128
constexpr int S_HGF  = S_BIAS + 768;             // hgru split FULL 53 rows * 68 fl2 = 7208 fl (overreads spill into BF1: harmless)
constexpr int S_BF1  = S_HGF + 53 * 136;         // 32*132 fl2 = 8448
constexpr int S_BF2  = S_BF1 + 8448;             // 8448
constexpr int S_KF   = S_BF2 + 8448;             // k split FULL: 56 rows * 132 fl2 = 14784 (rows 53-55 garbage-read ok)
constexpr int SM_FLOATS = S_KF + 56 * 264;       // 57560
constexpr int SM_BYTES  = SM_FLOATS * 4;         // 230,240 B

// 8-warp tensor-core MLP (R8 geometry): warp_m = wid&1, warp_n = wid>>1 (32 cols), 3xTF32.
// OUTMODE 0: relu+split local rows (fl2, stride Sout)
// OUTMODE 3: split (no relu) local rows (fl2, stride Sout)
// OUTMODE 4: split (no relu) GLOBAL rows into KF (stride 132 fl2) + peer fl2 push
template<int K, int OUTMODE>
__device__ __forceinline__ void mma_mlp(float* __restrict__ sm, int inOff, int Sin, int outOff, int Sout,
                                        const float4* __restrict__ gw, int biasOff,
                                        int wid, int lane, int c_lo, int c_n, uint32_t peer)
{
    const int warp_m = wid & 1, warp_n = wid >> 1;
    const int g = lane >> 2, l4 = lane & 3;
    constexpr int NC = K / 16;
    const float2* in2 = (const float2*)(sm + inOff);

    float acc[4][4];
#pragma unroll
    for (int i = 0; i < 4; i++)
#pragma unroll
        for (int j = 0; j < 4; j++) acc[i][j] = 0.f;

    float4 bb[2][8];
#pragma unroll
    for (int i = 0; i < 8; i++) bb[0][i] = gw[warp_n * 256 + i * 32 + lane];

    const int r0 = warp_m * 16 + g;
#pragma unroll 2
    for (int kc = 0; kc < NC; kc++){
        const int cur = kc & 1;
        if (kc + 1 < NC){
#pragma unroll
            for (int i = 0; i < 8; i++)
                bb[cur ^ 1][i] = gw[((kc + 1) * 4 + warp_n) * 256 + i * 32 + lane];
        }
#pragma unroll
        for (int ks = 0; ks < 2; ks++){
            const int kk = kc * 16 + ks * 8 + l4;
            float2 a0 = in2[r0 * Sin + kk];
            float2 a1 = in2[(r0 + 8) * Sin + kk];
            float2 a2 = in2[r0 * Sin + kk + 4];
            float2 a3 = in2[(r0 + 8) * Sin + kk + 4];
            uint32_t ahi[4] = {__float_as_uint(a0.x), __float_as_uint(a1.x), __float_as_uint(a2.x), __float_as_uint(a3.x)};
            uint32_t alo[4] = {__float_as_uint(a0.y), __float_as_uint(a1.y), __float_as_uint(a2.y), __float_as_uint(a3.y)};
#pragma unroll
            for (int nt = 0; nt < 4; nt++){
                float4 w = bb[cur][ks * 4 + nt];
                uint32_t bhi[2] = {__float_as_uint(w.x), __float_as_uint(w.z)};
                uint32_t blo[2] = {__float_as_uint(w.y), __float_as_uint(w.w)};
                mma_tf32(acc[nt], ahi, bhi);
                mma_tf32(acc[nt], ahi, blo);
                mma_tf32(acc[nt], alo, bhi);
            }
        }
    }

    const float* sbias = sm + biasOff;
    const int row0 = r0, row1 = r0 + 8;
    const bool ok0 = row0 < c_n, ok1 = row1 < c_n;
#pragma unroll
    for (int nt = 0; nt < 4; nt++){
        const int n0 = warp_n * 32 + nt * 8 + 2 * l4;
        const float b0 = sbias[n0], b1 = sbias[n0 + 1];
        float v00 = acc[nt][0] + b0, v01 = acc[nt][1] + b1;
        float v10 = acc[nt][2] + b0, v11 = acc[nt][3] + b1;
        if (OUTMODE == 0){
            v00 = fmaxf(v00, 0.f); v01 = fmaxf(v01, 0.f);
            v10 = fmaxf(v10, 0.f); v11 = fmaxf(v11, 0.f);
        }
        if (OUTMODE == 0 || OUTMODE == 3){
            float2* o2 = (float2*)(sm + outOff);
            if (ok0){ o2[row0 * Sout + n0] = split_tf32(v00); o2[row0 * Sout + n0 + 1] = split_tf32(v01); }
            if (ok1){ o2[row1 * Sout + n0] = split_tf32(v10); o2[row1 * Sout + n0 + 1] = split_tf32(v11); }
        } else {
            float2* kf = (float2*)(sm + S_KF);
            if (ok0){
                int c = c_lo + row0;
                float2 s0 = split_tf32(v00), s1 = split_tf32(v01);
                kf[c * 132 + n0] = s0;     st_peer2(&kf[c * 132 + n0], s0, peer);
                kf[c * 132 + n0 + 1] = s1; st_peer2(&kf[c * 132 + n0 + 1], s1, peer);
            }
            if (ok1){
                int c = c_lo + row1;
                float2 s0 = split_tf32(v10), s1 = split_tf32(v11);
                kf[c * 132 + n0] = s0;     st_peer2(&kf[c * 132 + n0], s0, peer);
                kf[c * 132 + n0 + 1] = s1; st_peer2(&kf[c * 132 + n0 + 1], s1, peer);
            }
        }
    }
}

// Stage C on tensor cores: TR(own rows x 53) = q(own,128) @ k(53,128)^T, 3xTF32.
// A = q split (BF1, local rows, stride 132 fl2); B = k split (KF, global rows, stride 132 fl2).
__device__ __forceinline__ void mma_transfer(float* __restrict__ sm, int wid, int lane, int c_n)
{
    const int warp_m = wid & 1, warp_n = wid >> 1;
    const int g = lane >> 2, l4 = lane & 3;
    const float2* A2 = (const float2*)(sm + S_BF1);
    const float2* B2 = (const float2*)(sm + S_KF);

    float acc[2][4];
#pragma unroll
    for (int i = 0; i < 2; i++)
#pragma unroll
        for (int j = 0; j < 4; j++) acc[i][j] = 0.f;

    const int r0 = warp_m * 16 + g;
#pragma unroll 4
    for (int ks = 0; ks < 16; ks++){
        const int kk = ks * 8 + l4;
        float2 a0 = A2[r0 * 132 + kk];
        float2 a1 = A2[(r0 + 8) * 132 + kk];
        float2 a2 = A2[r0 * 132 + kk + 4];
        float2 a3 = A2[(r0 + 8) * 132 + kk + 4];
        uint32_t ahi[4] = {__float_as_uint(a0.x), __float_as_uint(a1.x), __float_as_uint(a2.x), __float_as_uint(a3.x)};
        uint32_t alo[4] = {__float_as_uint(a0.y), __float_as_uint(a1.y), __float_as_uint(a2.y), __float_as_uint(a3.y)};
#pragma unroll
        for (int nt = 0; nt < 2; nt++){
            if (warp_n == 3 && nt == 1) continue;
            const int n = warp_n * 16 + nt * 8 + g;
            float2 b0 = B2[n * 132 + kk];
            float2 b1 = B2[n * 132 + kk + 4];
            uint32_t bhi[2] = {__float_as_uint(b0.x), __float_as_uint(b1.x)};
            uint32_t blo[2] = {__float_as_uint(b0.y), __float_as_uint(b1.y)};
            mma_tf32(acc[nt], ahi, bhi);
            mma_tf32(acc[nt], ahi, blo);
            mma_tf32(acc[nt], alo, bhi);
        }
    }

    const int row0 = r0, row1 = r0 + 8;
    const bool ok0 = row0 < c_n, ok1 = row1 < c_n;
#pragma unroll
    for (int nt = 0; nt < 2; nt++){
        if (warp_n == 3 && nt == 1) continue;
        const int n0 = warp_n * 16 + nt * 8 + 2 * l4;
        if (ok0){
            if (n0 < 53)     sm[S_TR + row0 * 56 + n0]     = acc[nt][0];
            if (n0 + 1 < 53) sm[S_TR + row0 * 56 + n0 + 1] = acc[nt][1];
        }
        if (ok1){
            if (n0 < 53)     sm[S_TR + row1 * 56 + n0]     = acc[nt][2];
            if (n0 + 1 < 53) sm[S_TR + row1 * 56 + n0 + 1] = acc[nt][3];
        }
    }
}

__global__ void __cluster_dims__(2, 1, 1) __launch_bounds__(256, 1)
recurrent_kernel(const float* __restrict__ x,
                 const float* __restrict__ b_hh,
                 const float* __restrict__ qb0, const float* __restrict__ qb1, const float* __restrict__ qb2,
                 const float* __restrict__ kb0, const float* __restrict__ kb1, const float* __restrict__ kb2,
                 const float* __restrict__ gate_bias,
                 const float* __restrict__ pred_w, const float* __restrict__ pred_b,
                 float* __restrict__ out_mix, float* __restrict__ out_fnc, float* __restrict__ out_pred)
{
    extern __shared__ float sm[];
    const int tid = threadIdx.x;
    const int b = blockIdx.x >> 1;
    const uint32_t rank = blockIdx.x & 1;
    const uint32_t peer = rank ^ 1;
    const int c_lo = rank ? 27 : 0;
    const int c_n  = rank ? 26 : 27;

    for (int i = tid; i < kC * kH; i += 256) sm[S_H + i] = 0.f;
    for (int i = tid; i < 64 * 192; i += 256) sm[S_WHH + i] = g_whht[i];
    for (int i = tid; i < SM_FLOATS - S_HGF; i += 256) sm[S_HGF + i] = 0.f;
    if (tid < 192){ sm[S_UV + tid] = g_u[tid]; sm[S_UV + 192 + tid] = g_v[tid]; sm[S_BHH + tid] = b_hh[tid]; }
    if (tid < 64) sm[S_PW + tid] = pred_w[tid];
    if (tid < 128){
        sm[S_BIAS + tid]       = kb0[tid];
        sm[S_BIAS + 128 + tid] = kb1[tid];
        sm[S_BIAS + 256 + tid] = kb2[tid];
        sm[S_BIAS + 384 + tid] = qb0[tid];
        sm[S_BIAS + 512 + tid] = qb1[tid];
        sm[S_BIAS + 640 + tid] = qb2[tid];
    }
    const float predb = pred_b[0];
    __syncthreads();

    const int hh = tid & 63, cg = tid >> 6;
    const int lane = tid & 31, wid = tid >> 5;
    const int nloc = c_n * 53;

    float facc[6], gbr[6];
#pragma unroll
    for (int j = 0; j < 6; j++){
        facc[j] = 0.f;
        int idx = tid + j * 256;
        gbr[j] = (idx < nloc) ? gate_bias[c_lo * 53 + idx] : 0.f;
    }

    float xr = (tid < kC) ? x[((size_t)b * kT) * kC + tid] : 0.f;

    cluster_sync_();

    for (int t = 0; t < kT; t++){
        if (tid < kC) sm[S_X + tid] = xr;
        __syncthreads();
        {
            int tn = (t + 1 < kT) ? t + 1 : t;
            if (tid < kC) xr = x[((size_t)b * kT + tn) * kC + tid];
        }

        // ---- Stage A: FFMA GRU own rows; write hgru SPLIT full (global row) + peer fl2 ----
        {
            float aR[7], aZ[7], aN[7];
#pragma unroll
            for (int i = 0; i < 7; i++){ aR[i] = 0.f; aZ[i] = 0.f; aN[i] = 0.f; }
#pragma unroll 1
            for (int k = 0; k < 64; k += 4){
                float wr0 = sm[S_WHH + (k + 0) * 192 + hh];
                float wr1 = sm[S_WHH + (k + 1) * 192 + hh];
                float wr2 = sm[S_WHH + (k + 2) * 192 + hh];
                float wr3 = sm[S_WHH + (k + 3) * 192 + hh];
                float wz0 = sm[S_WHH + (k + 0) * 192 + 64 + hh];
                float wz1 = sm[S_WHH + (k + 1) * 192 + 64 + hh];
                float wz2 = sm[S_WHH + (k + 2) * 192 + 64 + hh];
                float wz3 = sm[S_WHH + (k + 3) * 192 + 64 + hh];
                float wn0 = sm[S_WHH + (k + 0) * 192 + 128 + hh];
                float wn1 = sm[S_WHH + (k + 1) * 192 + 128 + hh];
                float wn2 = sm[S_WHH + (k + 2) * 192 + 128 + hh];
                float wn3 = sm[S_WHH + (k + 3) * 192 + 128 + hh];
#pragma unroll
                for (int ci = 0; ci < 7; ci++){
                    int cl = cg + 4 * ci;
                    if (cl < c_n){
                        const float4 hv = *(const float4*)&sm[S_H + (c_lo + cl) * 64 + k];
                        aR[ci] += hv.x * wr0 + hv.y * wr1 + hv.z * wr2 + hv.w * wr3;
                        aZ[ci] += hv.x * wz0 + hv.y * wz1 + hv.z * wz2 + hv.w * wz3;
                        aN[ci] += hv.x * wn0 + hv.y * wn1 + hv.z * wn2 + hv.w * wn3;
                    }
                }
            }
            float2* hgf = (float2*)(sm + S_HGF);
#pragma unroll
            for (int ci = 0; ci < 7; ci++){
                int cl = cg + 4 * ci;
                if (cl < c_n){
                    int c = c_lo + cl;
                    float xi = sm[S_X + c];
                    float r = fast_sigmoid(fmaf(xi, sm[S_UV + hh],       sm[S_UV + 192 + hh]) + aR[ci] + sm[S_BHH + hh]);
                    float z = fast_sigmoid(fmaf(xi, sm[S_UV + 64 + hh],  sm[S_UV + 256 + hh]) + aZ[ci] + sm[S_BHH + 64 + hh]);
                    float n = fast_tanh(   fmaf(xi, sm[S_UV + 128 + hh], sm[S_UV + 320 + hh]) + r * (aN[ci] + sm[S_BHH + 128 + hh]));
                    float hg = (1.f - z) * n + z * sm[S_H + c * 64 + hh];
                    float2 s = split_tf32(hg);
                    hgf[c * 68 + hh] = s;
                    st_peer2(&hgf[c * 68 + hh], s, peer);
                }
            }
        }
        __syncthreads();

        // ---- Stage B: 6 tensor-core MLP layers (k chain then q chain) ----
        mma_mlp<64,  0>(sm, S_HGF + c_lo * 136, 68, S_BF1, 132, g_wk0, S_BIAS,       wid, lane, c_lo, c_n, peer); __syncthreads();
        mma_mlp<128, 0>(sm, S_BF1, 132, S_BF2, 132, g_wk1, S_BIAS + 128, wid, lane, c_lo, c_n, peer); __syncthreads();
        mma_mlp<128, 4>(sm, S_BF2, 132, 0, 0,       g_wk2, S_BIAS + 256, wid, lane, c_lo, c_n, peer); __syncthreads();
        mma_mlp<64,  0>(sm, S_HGF + c_lo * 136, 68, S_BF1, 132, g_wq0, S_BIAS + 384, wid, lane, c_lo, c_n, peer); __syncthreads();
        mma_mlp<128, 0>(sm, S_BF1, 132, S_BF2, 132, g_wq1, S_BIAS + 512, wid, lane, c_lo, c_n, peer); __syncthreads();
        mma_mlp<128, 3>(sm, S_BF2, 132, S_BF1, 132, g_wq2, S_BIAS + 640, wid, lane, c_lo, c_n, peer);

        cluster_sync_();   // full k split + full hgru split visible everywhere

        // ---- Stage C: tensor-core transfer = q @ k^T ----
        mma_transfer(sm, wid, lane, c_n);
        __syncthreads();

        // ---- norm ----
        {
            float p = 0.f;
            for (int idx = tid; idx < nloc; idx += 256){
                int cl = idx / 53, dd = idx - cl * 53;
                float v = sm[S_TR + cl * 56 + dd];
                p = fmaf(v, v, p);
            }
#pragma unroll
            for (int o = 16; o; o >>= 1) p += __shfl_xor_sync(0xffffffffu, p, o);
            if ((tid & 31) == 0) sm[S_RED + (tid >> 5)] = p;
        }
        __syncthreads();
        if (tid == 0){
            float s = 0.f;
            for (int i = 0; i < 8; i++) s += sm[S_RED + i];
            sm[S_RED + 10] = s;
            st_peer(&sm[S_RED + 11], s, peer);
        }
        cluster_sync_();
        const float inv = rsqrtf(sm[S_RED + 10] + sm[S_RED + 11]);

        // ---- normalize + gate + emit mix + reg-FNC ----
        {
            float* mix_bt = out_mix + ((size_t)b * kT + t) * kC2;
            float* mixp_bt = g_mixp + ((size_t)b * kT + t) * kKP0;
#pragma unroll
            for (int j = 0; j < 6; j++){
                int idx = tid + j * 256;
                if (idx < nloc){
                    int glob = c_lo * 53 + idx;
                    int cl = idx / 53, dd = idx - cl * 53;
                    float v = sm[S_TR + cl * 56 + dd] * inv;
                    float gate = fast_sigmoid(fabsf(v) + gbr[j]);
                    float val = v * gate;
                    sm[S_TR + cl * 56 + dd] = val;
                    mix_bt[glob] = val;
                    mixp_bt[glob] = __uint_as_float(cvt_tf32(val));
                    facc[j] += val;
                }
            }
        }
        __syncthreads();

        // ---- Stage D: h_new = transfer(own) @ hgru(full via split) ----
        {
            const float2* hgf = (const float2*)(sm + S_HGF);
            float acc[7];
#pragma unroll
            for (int i = 0; i < 7; i++) acc[i] = 0.f;
#pragma unroll 1
            for (int d = 0; d < 52; d += 4){
                float2 h0 = hgf[(d + 0) * 68 + hh];
                float2 h1 = hgf[(d + 1) * 68 + hh];
                float2 h2 = hgf[(d + 2) * 68 + hh];
                float2 h3 = hgf[(d + 3) * 68 + hh];
                float g0 = h0.x + h0.y, g1 = h1.x + h1.y, g2 = h2.x + h2.y, g3 = h3.x + h3.y;
#pragma unroll
                for (int ci = 0; ci < 7; ci++){
                    int cl = cg + 4 * ci;
                    if (cl < c_n){
                        const float4 tv = *(const float4*)&sm[S_TR + cl * 56 + d];
                        acc[ci] += tv.x * g0 + tv.y * g1 + tv.z * g2 + tv.w * g3;
                    }
                }
            }
            {
                float2 hl = hgf[52 * 68 + hh];
                float g = hl.x + hl.y;
#pragma unroll
                for (int ci = 0; ci < 7; ci++){
                    int cl = cg + 4 * ci;
                    if (cl < c_n) acc[ci] += sm[S_TR + cl * 56 + 52] * g;
                }
            }
#pragma unroll
            for (int ci = 0; ci < 7; ci++){
                int cl = cg + 4 * ci;
                if (cl < c_n) sm[S_H + (c_lo + cl) * 64 + hh] = acc[ci];
            }
        }
        __syncthreads();

        if (t < kT - 1 && tid < c_n){
            int c = c_lo + tid;
            float s2 = 0.f;
#pragma unroll
            for (int k = 0; k < 64; k += 4){
                const float4 hv = *(const float4*)&sm[S_H + c * 64 + k];
                s2 += hv.x * sm[S_PW + k] + hv.y * sm[S_PW + k + 1] + hv.z * sm[S_PW + k + 2] + hv.w * sm[S_PW + k + 3];
            }
            out_pred[((size_t)b * (kT - 1) + t) * kC + c] = s2 + predb;
        }

        cluster_sync_();
    }

#pragma unroll
    for (int j = 0; j < 6; j++){
        int idx = tid + j * 256;
        if (idx < nloc)
            out_fnc[(size_t)b * kC2 + c_lo * 53 + idx] = facc[j] * (1.f / 256.f);
    }
}

// ---------------- tf32 tensor-core classifier GEMM ----------------
template<bool RELU, bool CVT>
__global__ __launch_bounds__(256, 2) void mma_gemm(const float* __restrict__ A, const float* __restrict__ B,
                                                   const float* __restrict__ bias, float* __restrict__ C,
                                                   int M, int Nstore, int Nreal, int K)
{
    extern __shared__ float smg[];
    float* As = smg;
    float* Bs = smg + 2 * 4608;

    const int tid = threadIdx.x;
    const int wid = tid >> 5, lane = tid & 31;
    const int warp_m = wid & 3, warp_n = wid >> 2;
    const int g = lane >> 2, l4 = lane & 3;
    const int bm = blockIdx.y * 128, bn = blockIdx.x * 128;

    const float* Ab = A + (size_t)bm * K;
    const float* Bb = B + (size_t)bn * K;

    float acc[2][8][4];
#pragma unroll
    for (int i = 0; i < 2; i++)
#pragma unroll
        for (int j = 0; j < 8; j++)
#pragma unroll
            for (int q = 0; q < 4; q++) acc[i][j][q] = 0.f;

    const int nk = K >> 5;

    auto load_tile = [&](int kt, int buf){
        const int k0 = kt * 32;
        float* as = As + buf * 4608;
        float* bs = Bs + buf * 4608;
#pragma unroll
        for (int i = 0; i < 4; i++){
            int ch = tid + i * 256;
            int row = ch >> 3;
            int ko = (ch & 7) * 4;
            cp_async16(&as[row * 36 + ko], Ab + (size_t)row * K + k0 + ko);
            cp_async16(&bs[row * 36 + ko], Bb + (size_t)row * K + k0 + ko);
        }
        asm volatile("cp.async.commit_group;" ::: "memory");
    };

    load_tile(0, 0);

    for (int kt = 0; kt < nk; kt++){
        const int buf = kt & 1;
        if (kt + 1 < nk){
            load_tile(kt + 1, buf ^ 1);
            asm volatile("cp.async.wait_group 1;" ::: "memory");
        } else {
            asm volatile("cp.async.wait_group 0;" ::: "memory");
        }
        __syncthreads();

        const float* as = As + buf * 4608;
        const float* bs = Bs + buf * 4608;
#pragma unroll
        for (int s = 0; s < 4; s++){
            const int kk = s * 8 + l4;
            uint32_t a[2][4], bf[8][2];
            const int r0 = warp_m * 32 + g;
            a[0][0] = __float_as_uint(as[(r0     ) * 36 + kk]);
            a[0][1] = __float_as_uint(as[(r0 +  8) * 36 + kk]);
            a[0][2] = __float_as_uint(as[(r0     ) * 36 + kk + 4]);
            a[0][3] = __float_as_uint(as[(r0 +  8) * 36 + kk + 4]);
            a[1][0] = __float_as_uint(as[(r0 + 16) * 36 + kk]);
            a[1][1] = __float_as_uint(as[(r0 + 24) * 36 + kk]);
            a[1][2] = __float_as_uint(as[(r0 + 16) * 36 + kk + 4]);
            a[1][3] = __float_as_uint(as[(r0 + 24) * 36 + kk + 4]);
#pragma unroll
            for (int nt = 0; nt < 8; nt++){
                const int nb = warp_n * 64 + nt * 8 + g;
                bf[nt][0] = __float_as_uint(bs[nb * 36 + kk]);
                bf[nt][1] = __float_as_uint(bs[nb * 36 + kk + 4]);
            }
#pragma unroll
            for (int mt = 0; mt < 2; mt++)
#pragma unroll
                for (int nt = 0; nt < 8; nt++)
                    mma_tf32(acc[mt][nt], a[mt], bf[nt]);
        }
        __syncthreads();
    }

#pragma unroll
    for (int mt = 0; mt < 2; mt++){
#pragma unroll
        for (int nt = 0; nt < 8; nt++){
            const int row = bm + warp_m * 32 + mt * 16 + g;
            const int col = bn + warp_n * 64 + nt * 8 + 2 * l4;
            const float b0v = (col < Nreal) ? bias[col] : 0.f;
            const float b1v = (col + 1 < Nreal) ? bias[col + 1] : 0.f;
            float v00 = acc[mt][nt][0] + b0v;
            float v01 = acc[mt][nt][1] + b1v;
            float v10 = acc[mt][nt][2] + b0v;
            float v11 = acc[mt][nt][3] + b1v;
            if (RELU){
                v00 = fmaxf(v00, 0.f); v01 = fmaxf(v01, 0.f);
                v10 = fmaxf(v10, 0.f); v11 = fmaxf(v11, 0.f);
            }
            if (CVT){
                v00 = __uint_as_float(cvt_tf32(v00)); v01 = __uint_as_float(cvt_tf32(v01));
                v10 = __uint_as_float(cvt_tf32(v10)); v11 = __uint_as_float(cvt_tf32(v11));
            }
            C[(size_t)row * Nstore + col]           = v00;
            C[(size_t)row * Nstore + col + 1]       = v01;
            C[(size_t)(row + 8) * Nstore + col]     = v10;
            C[(size_t)(row + 8) * Nstore + col + 1] = v11;
        }
    }
}

__global__ void zbar_kernel()
{
    const int b = blockIdx.x;
    for (int j = threadIdx.x; j < kN2; j += blockDim.x){
        float s = 0.f;
        for (int t = 0; t < kT; t++) s += g_z2[((size_t)b * kT + t) * kNP2 + j];
        g_zbar[b * kN2 + j] = s * (1.f / (float)kT);
    }
}

__global__ void logits_kernel(const float* __restrict__ w2, const float* __restrict__ b2, float* __restrict__ out)
{
    __shared__ float red[8];
    const int b = blockIdx.x >> 1, o = blockIdx.x & 1;
    float s = 0.f;
    for (int j = threadIdx.x; j < kN2; j += 256)
        s += g_zbar[b * kN2 + j] * w2[o * kN2 + j];
#pragma unroll
    for (int off = 16; off; off >>= 1) s += __shfl_xor_sync(0xffffffffu, s, off);
    if ((threadIdx.x & 31) == 0) red[threadIdx.x >> 5] = s;
    __syncthreads();
    if (threadIdx.x == 0){
        float t = 0.f;
        for (int i = 0; i < 8; i++) t += red[i];
        out[b * 2 + o] = t + b2[o];
    }
}

__global__ void xcopy_kernel(const float* __restrict__ x, float* __restrict__ outx)
{
    const int n = kB * (kT - 1) * kC;
    for (int idx = blockIdx.x * blockDim.x + threadIdx.x; idx < n; idx += gridDim.x * blockDim.x){
        int b = idx / ((kT - 1) * kC);
        int r = idx - b * (kT - 1) * kC;
        outx[idx] = x[(size_t)b * kT * kC + kC + r];
    }
}

extern "C" void kernel_launch(void* const* d_in, const int* in_sizes, int n_in,
                              void* d_out, int out_size)
{
    const float* x        = (const float*)d_in[0];
    const float* w_emb    = (const float*)d_in[1];
    const float* b_emb    = (const float*)d_in[2];
    const float* w_ih     = (const float*)d_in[3];
    const float* w_hh     = (const float*)d_in[4];
    const float* b_ih     = (const float*)d_in[5];
    const float* b_hh     = (const float*)d_in[6];
    const float* q_w0     = (const float*)d_in[7];
    const float* q_b0     = (const float*)d_in[8];
    const float* q_w1     = (const float*)d_in[9];
    const float* q_b1     = (const float*)d_in[10];
    const float* q_w2     = (const float*)d_in[11];
    const float* q_b2     = (const float*)d_in[12];
    const float* k_w0     = (const float*)d_in[13];
    const float* k_b0     = (const float*)d_in[14];
    const float* k_w1     = (const float*)d_in[15];
    const float* k_b1     = (const float*)d_in[16];
    const float* k_w2     = (const float*)d_in[17];
    const float* k_b2     = (const float*)d_in[18];
    const float* gate_bias= (const float*)d_in[19];
    const float* pred_w   = (const float*)d_in[20];
    const float* pred_b   = (const float*)d_in[21];
    const float* clf_w0   = (const float*)d_in[22];
    const float* clf_b0   = (const float*)d_in[23];
    const float* clf_w1   = (const float*)d_in[24];
    const float* clf_b1   = (const float*)d_in[25];
    const float* clf_w2   = (const float*)d_in[26];
    const float* clf_b2   = (const float*)d_in[27];

    float* out      = (float*)d_out;
    float* out_log  = out;
    float* out_fnc  = out + 2 * kB;
    float* out_mix  = out_fnc + (size_t)kB * kC2;
    float* out_pred = out_mix + (size_t)kB * kT * kC2;
    float* out_x    = out_pred + (size_t)kB * (kT - 1) * kC;

    cudaFuncSetAttribute(recurrent_kernel, cudaFuncAttributeMaxDynamicSharedMemorySize, SM_BYTES);
    cudaFuncSetAttribute(mma_gemm<true, true>,  cudaFuncAttributeMaxDynamicSharedMemorySize, 2 * 2 * 4608 * 4);
    cudaFuncSetAttribute(mma_gemm<true, false>, cudaFuncAttributeMaxDynamicSharedMemorySize, 2 * 2 * 4608 * 4);

    prep_small<<<48, 256>>>(w_ih, w_emb, b_emb, b_ih, w_hh);
    prep_frag<<<32, 256>>>(q_w0, q_w1, q_w2, k_w0, k_w1, k_w2);
    pack_clf<<<2048, 256>>>(clf_w0, clf_w1);

    recurrent_kernel<<<2 * kB, 256, SM_BYTES>>>(x, b_hh, q_b0, q_b1, q_b2, k_b0, k_b1, k_b2,
                                                gate_bias, pred_w, pred_b,
                                                out_mix, out_fnc, out_pred);

    float *pz1, *pz2, *pw0p, *pw1p, *pmixp;
    cudaGetSymbolAddress((void**)&pz1,   g_z1);
    cudaGetSymbolAddress((void**)&pz2,   g_z2);
    cudaGetSymbolAddress((void**)&pw0p,  g_w0p);
    cudaGetSymbolAddress((void**)&pw1p,  g_w1p);
    cudaGetSymbolAddress((void**)&pmixp, g_mixp);

    const int smem_gemm = 2 * 2 * 4608 * 4;
    mma_gemm<true, true ><<<dim3(kNP1 / 128, kM / 128), 256, smem_gemm>>>(pmixp, pw0p, clf_b0, pz1, kM, kNP1, kN1, kKP0);
    mma_gemm<true, false><<<dim3(kNP2 / 128, kM / 128), 256, smem_gemm>>>(pz1,   pw1p, clf_b1, pz2, kM, kNP2, kN2, kNP1);

    zbar_kernel<<<kB, 256>>>();
    logits_kernel<<<2 * kB, 256>>>(clf_w2, clf_b2, out_log);
    xcopy_kernel<<<512, 256>>>(x, out_x);
}

// round 15
// speedup vs baseline: 1.0587x; 1.0361x over previous
#include <cuda_runtime.h>
#include <math.h>
#include <stdint.h>

static inline int cdiv(int a, int b){ return (a + b - 1) / b; }

constexpr int kB = 64, kT = 256, kC = 53, kH = 64, kA = 128;
constexpr int kC2 = kC * kC;
constexpr int kN1 = kC2 / 2;
constexpr int kN2 = kC2 / 4;
constexpr int kM  = kB * kT;
constexpr int kKP0 = 2816, kNP1 = 1408, kNP2 = 768;
constexpr int kTH = 512;                         // threads per CTA (16 warps)

__device__ float g_u[192], g_v[192];
__device__ float g_whht[64 * 192];
__device__ float4 g_wq0[4096], g_wq1[8192], g_wq2[8192];
__device__ float4 g_wk0[4096], g_wk1[8192], g_wk2[8192];
__device__ float g_mixp[(size_t)kM * kKP0];
__device__ float g_w0p[(size_t)kNP1 * kKP0];
__device__ float g_w1p[(size_t)kNP2 * kNP1];
__device__ float g_z1[(size_t)kM * kNP1];
__device__ float g_z2[(size_t)kM * kNP2];
__device__ float g_zbar[kB * kN2];

__device__ __forceinline__ float fast_sigmoid(float x){
    float e; asm("ex2.approx.f32 %0, %1;" : "=f"(e) : "f"(-x * 1.4426950408889634f));
    float r; asm("rcp.approx.f32 %0, %1;" : "=f"(r) : "f"(1.f + e));
    return r;
}
__device__ __forceinline__ float fast_tanh(float x){ return fmaf(2.f, fast_sigmoid(2.f * x), -1.f); }
__device__ __forceinline__ uint32_t cvt_tf32(float x){
    uint32_t y; asm("cvt.rna.tf32.f32 %0, %1;" : "=r"(y) : "f"(x)); return y;
}
__device__ __forceinline__ float2 split_tf32(float v){
    float hi = __uint_as_float(cvt_tf32(v));
    float lo = __uint_as_float(cvt_tf32(v - hi));
    return make_float2(hi, lo);
}
__device__ __forceinline__ void st_peer(float* p, float v, uint32_t peer){
    uint32_t l = (uint32_t)__cvta_generic_to_shared(p);
    uint32_t r; asm("mapa.shared::cluster.u32 %0, %1, %2;" : "=r"(r) : "r"(l), "r"(peer));
    asm volatile("st.shared::cluster.f32 [%0], %1;" :: "r"(r), "f"(v) : "memory");
}
__device__ __forceinline__ void cluster_sync_(){
    asm volatile("barrier.cluster.arrive.aligned;" ::: "memory");
    asm volatile("barrier.cluster.wait.aligned;" ::: "memory");
}
__device__ __forceinline__ void cp_async16(void* smem, const void* gmem){
    uint32_t s = (uint32_t)__cvta_generic_to_shared(smem);
    asm volatile("cp.async.cg.shared.global [%0], [%1], 16;" :: "r"(s), "l"(gmem) : "memory");
}
__device__ __forceinline__ void mma_tf32(float* c, const uint32_t* a, const uint32_t* b){
    asm volatile("mma.sync.aligned.m16n8k8.row.col.f32.tf32.tf32.f32 "
        "{%0,%1,%2,%3}, {%4,%5,%6,%7}, {%8,%9}, {%0,%1,%2,%3};"
        : "+f"(c[0]), "+f"(c[1]), "+f"(c[2]), "+f"(c[3])
        : "r"(a[0]), "r"(a[1]), "r"(a[2]), "r"(a[3]), "r"(b[0]), "r"(b[1]));
}

__global__ void prep_small(const float* __restrict__ w_ih, const float* __restrict__ w_emb,
                           const float* __restrict__ b_emb, const float* __restrict__ b_ih,
                           const float* __restrict__ w_hh)
{
    int gt = blockIdx.x * blockDim.x + threadIdx.x;
    int gs = gridDim.x * blockDim.x;
    for (int j = gt; j < 192; j += gs){
        float su = 0.f, sv = 0.f;
        for (int e = 0; e < 64; e++){
            su += w_ih[j * 64 + e] * w_emb[e];
            sv += w_ih[j * 64 + e] * b_emb[e];
        }
        g_u[j] = su; g_v[j] = sv + b_ih[j];
    }
    for (int idx = gt; idx < 64 * 192; idx += gs){
        int k = idx / 192, j = idx - k * 192;
        g_whht[idx] = w_hh[j * 64 + k];
    }
}

// bake W (N=128 x K) into mma B-fragment order (4 x 32-col blocks)
__device__ __forceinline__ void bake_one(float4* dst, const float* W, int K, int idx){
    int kc = idx >> 10, rem = idx & 1023;
    int wn = rem >> 8, r2 = rem & 255;
    int grp = r2 >> 5, lane = r2 & 31;
    int ks = grp >> 2, nt = grp & 3;
    int n = wn * 32 + nt * 8 + (lane >> 2);
    int k = kc * 16 + ks * 8 + (lane & 3);
    float v0 = W[n * K + k], v1 = W[n * K + k + 4];
    float h0 = __uint_as_float(cvt_tf32(v0));
    float h1 = __uint_as_float(cvt_tf32(v1));
    dst[idx] = make_float4(h0, __uint_as_float(cvt_tf32(v0 - h0)),
                           h1, __uint_as_float(cvt_tf32(v1 - h1)));
}

__global__ void prep_frag(const float* __restrict__ qw0, const float* __restrict__ qw1, const float* __restrict__ qw2,
                          const float* __restrict__ kw0, const float* __restrict__ kw1, const float* __restrict__ kw2)
{
    int gt = blockIdx.x * blockDim.x + threadIdx.x;
    int gs = gridDim.x * blockDim.x;
    for (int i = gt; i < 4096; i += gs){ bake_one(g_wq0, qw0, 64, i); bake_one(g_wk0, kw0, 64, i); }
    for (int i = gt; i < 8192; i += gs){
        bake_one(g_wq1, qw1, 128, i); bake_one(g_wq2, qw2, 128, i);
        bake_one(g_wk1, kw1, 128, i); bake_one(g_wk2, kw2, 128, i);
    }
}

__global__ void pack_clf(const float* __restrict__ clf_w0, const float* __restrict__ clf_w1)
{
    size_t gt = (size_t)blockIdx.x * blockDim.x + threadIdx.x;
    size_t gs = (size_t)gridDim.x * blockDim.x;
    for (size_t idx = gt; idx < (size_t)kNP1 * kKP0; idx += gs){
        int j = (int)(idx / kKP0), k = (int)(idx - (size_t)j * kKP0);
        float v = (j < kN1 && k < kC2) ? clf_w0[(size_t)j * kC2 + k] : 0.f;
        g_w0p[idx] = __uint_as_float(cvt_tf32(v));
    }
    for (size_t idx = gt; idx < (size_t)kNP2 * kNP1; idx += gs){
        int j = (int)(idx / kNP1), k = (int)(idx - (size_t)j * kNP1);
        float v = (j < kN2 && k < kN1) ? clf_w1[(size_t)j * kN1 + k] : 0.f;
        g_w1p[idx] = __uint_as_float(cvt_tf32(v));
    }
}

// ---------------- smem layout (floats) — identical to R8 except S_RED=24 ----------------
constexpr int S_H    = 0;                        // 53*64 fp32 h (own rows)
constexpr int S_HGRU = S_H + kC * kH;            // 53*64 fp32 full (peer pushed)
constexpr int S_B2   = S_HGRU + kC * kH;         // KT 128*53 full (peer pushed)
constexpr int S_QF   = S_B2 + 128 * 53;          // q fp32 32*132 (local rows)
constexpr int S_TR   = S_QF + 32 * 132;          // 53*56
constexpr int S_WHH  = S_TR + kC * 56;           // 64*192
constexpr int S_UV   = S_WHH + 64 * 192;         // 384
constexpr int S_BHH  = S_UV + 384;               // 192
constexpr int S_PW   = S_BHH + 192;              // 64
constexpr int S_X    = S_PW + 64;                // 56
constexpr int S_RED  = S_X + 56;                 // 24 (16 warp partials + s slots)
constexpr int S_BIAS = S_RED + 24;               // 6*128
constexpr int S_HG2  = S_BIAS + 768;             // 32*68 float2
constexpr int S_BF1  = S_HG2 + 4352;             // 32*132 float2
constexpr int S_BF2  = S_BF1 + 8448;
constexpr int SM_FLOATS = S_BF2 + 8448;
constexpr int SM_BYTES  = SM_FLOATS * 4;

// 16-warp tensor-core MLP: warp_m = wid&1 (16 rows), warp_n = wid>>1 (16 cols each), 3xTF32.
// OUTMODE 0: relu+split->float2 stride Sout; 1: fp32 stride132; 2: KT[n*53+c]+peer
template<int K, int OUTMODE>
__device__ __forceinline__ void mma_mlp(float* __restrict__ sm, int inOff, int Sin, int outOff, int Sout,
                                        const float4* __restrict__ gw, int biasOff,
                                        int wid, int lane, int c_lo, int c_n, uint32_t peer)
{
    const int warp_m = wid & 1, warp_n = wid >> 1;     // warp_n 0..7
    const int wn32 = warp_n >> 1, ntbase = (warp_n & 1) * 2;
    const int g = lane >> 2, l4 = lane & 3;
    constexpr int NC = K / 16;
    const float2* in2 = (const float2*)(sm + inOff);

    float acc[2][4];
#pragma unroll
    for (int i = 0; i < 2; i++)
#pragma unroll
        for (int j = 0; j < 4; j++) acc[i][j] = 0.f;

    float4 bb[2][4];
#pragma unroll
    for (int ks2 = 0; ks2 < 2; ks2++)
#pragma unroll
        for (int nt = 0; nt < 2; nt++)
            bb[0][ks2 * 2 + nt] = gw[wn32 * 256 + (ks2 * 4 + ntbase + nt) * 32 + lane];

    const int r0 = warp_m * 16 + g;
#pragma unroll 2
    for (int kc = 0; kc < NC; kc++){
        const int cur = kc & 1;
        if (kc + 1 < NC){
#pragma unroll
            for (int ks2 = 0; ks2 < 2; ks2++)
#pragma unroll
                for (int nt = 0; nt < 2; nt++)
                    bb[cur ^ 1][ks2 * 2 + nt] = gw[((kc + 1) * 4 + wn32) * 256 + (ks2 * 4 + ntbase + nt) * 32 + lane];
        }
#pragma unroll
        for (int ks = 0; ks < 2; ks++){
            const int kk = kc * 16 + ks * 8 + l4;
            float2 a0 = in2[r0 * Sin + kk];
            float2 a1 = in2[(r0 + 8) * Sin + kk];
            float2 a2 = in2[r0 * Sin + kk + 4];
            float2 a3 = in2[(r0 + 8) * Sin + kk + 4];
            uint32_t ahi[4] = {__float_as_uint(a0.x), __float_as_uint(a1.x), __float_as_uint(a2.x), __float_as_uint(a3.x)};
            uint32_t alo[4] = {__float_as_uint(a0.y), __float_as_uint(a1.y), __float_as_uint(a2.y), __float_as_uint(a3.y)};
#pragma unroll
            for (int nt = 0; nt < 2; nt++){
                float4 w = bb[cur][ks * 2 + nt];
                uint32_t bhi[2] = {__float_as_uint(w.x), __float_as_uint(w.z)};
                uint32_t blo[2] = {__float_as_uint(w.y), __float_as_uint(w.w)};
                mma_tf32(acc[nt], ahi, bhi);
                mma_tf32(acc[nt], ahi, blo);
                mma_tf32(acc[nt], alo, bhi);
            }
        }
    }

    const float* sbias = sm + biasOff;
    const int row0 = r0, row1 = r0 + 8;
    const bool ok0 = row0 < c_n, ok1 = row1 < c_n;
#pragma unroll
    for (int nt = 0; nt < 2; nt++){
        const int n0 = warp_n * 16 + nt * 8 + 2 * l4;
        const float b0 = sbias[n0], b1 = sbias[n0 + 1];
        float v00 = acc[nt][0] + b0, v01 = acc[nt][1] + b1;
        float v10 = acc[nt][2] + b0, v11 = acc[nt][3] + b1;
        if (OUTMODE == 0){
            v00 = fmaxf(v00, 0.f); v01 = fmaxf(v01, 0.f);
            v10 = fmaxf(v10, 0.f); v11 = fmaxf(v11, 0.f);
            float2* o2 = (float2*)(sm + outOff);
            if (ok0){ o2[row0 * Sout + n0] = split_tf32(v00); o2[row0 * Sout + n0 + 1] = split_tf32(v01); }
            if (ok1){ o2[row1 * Sout + n0] = split_tf32(v10); o2[row1 * Sout + n0 + 1] = split_tf32(v11); }
        } else if (OUTMODE == 1){
            float* oq = sm + outOff;
            if (ok0){ oq[row0 * 132 + n0] = v00; oq[row0 * 132 + n0 + 1] = v01; }
            if (ok1){ oq[row1 * 132 + n0] = v10; oq[row1 * 132 + n0 + 1] = v11; }
        } else {
            float* kt = sm + outOff;
            if (ok0){
                int c = c_lo + row0;
                kt[n0 * 53 + c] = v00;       st_peer(&kt[n0 * 53 + c], v00, peer);
                kt[(n0 + 1) * 53 + c] = v01; st_peer(&kt[(n0 + 1) * 53 + c], v01, peer);
            }
            if (ok1){
                int c = c_lo + row1;
                kt[n0 * 53 + c] = v10;       st_peer(&kt[n0 * 53 + c], v10, peer);
                kt[(n0 + 1) * 53 + c] = v11; st_peer(&kt[(n0 + 1) * 53 + c], v11, peer);
            }
        }
    }
}

__global__ void __cluster_dims__(2, 1, 1) __launch_bounds__(kTH, 1)
recurrent_kernel(const float* __restrict__ x,
                 const float* __restrict__ b_hh,
                 const float* __restrict__ qb0, const float* __restrict__ qb1, const float* __restrict__ qb2,
                 const float* __restrict__ kb0, const float* __restrict__ kb1, const float* __restrict__ kb2,
                 const float* __restrict__ gate_bias,
                 const float* __restrict__ pred_w, const float* __restrict__ pred_b,
                 float* __restrict__ out_mix, float* __restrict__ out_fnc, float* __restrict__ out_pred)
{
    extern __shared__ float sm[];
    const int tid = threadIdx.x;
    const int b = blockIdx.x >> 1;
    const uint32_t rank = blockIdx.x & 1;
    const uint32_t peer = rank ^ 1;
    const int c_lo = rank ? 27 : 0;
    const int c_n  = rank ? 26 : 27;

    for (int i = tid; i < kC * kH; i += kTH) sm[S_H + i] = 0.f;
    for (int i = tid; i < 64 * 192; i += kTH) sm[S_WHH + i] = g_whht[i];
    for (int i = tid; i < SM_FLOATS - S_HG2; i += kTH) sm[S_HG2 + i] = 0.f;
    if (tid < 192){ sm[S_UV + tid] = g_u[tid]; sm[S_UV + 192 + tid] = g_v[tid]; sm[S_BHH + tid] = b_hh[tid]; }
    if (tid < 64) sm[S_PW + tid] = pred_w[tid];
    if (tid < 128){
        sm[S_BIAS + tid]       = kb0[tid];
        sm[S_BIAS + 128 + tid] = kb1[tid];
        sm[S_BIAS + 256 + tid] = kb2[tid];
        sm[S_BIAS + 384 + tid] = qb0[tid];
        sm[S_BIAS + 512 + tid] = qb1[tid];
        sm[S_BIAS + 640 + tid] = qb2[tid];
    }
    const float predb = pred_b[0];
    __syncthreads();

    const int hh = tid & 63, cg = tid >> 6;          // cg 0..7
    const int lane = tid & 31, wid = tid >> 5;       // wid 0..15
    const int nloc = c_n * 53;

    float facc[3], gbr[3];
#pragma unroll
    for (int j = 0; j < 3; j++){
        facc[j] = 0.f;
        int idx = tid + j * kTH;
        gbr[j] = (idx < nloc) ? gate_bias[c_lo * 53 + idx] : 0.f;
    }

    float xr = (tid < kC) ? x[((size_t)b * kT) * kC + tid] : 0.f;

    cluster_sync_();

    for (int t = 0; t < kT; t++){
        if (tid < kC) sm[S_X + tid] = xr;
        __syncthreads();
        {
            int tn = (t + 1 < kT) ? t + 1 : t;
            if (tid < kC) xr = x[((size_t)b * kT + tn) * kC + tid];
        }

        // ---- Stage A: GRU own rows (4 row-slices/thread); hgru fp32 (own+peer) + split ----
        {
            float aR[4], aZ[4], aN[4];
#pragma unroll
            for (int i = 0; i < 4; i++){ aR[i] = 0.f; aZ[i] = 0.f; aN[i] = 0.f; }
#pragma unroll 1
            for (int k = 0; k < 64; k += 4){
                float wr0 = sm[S_WHH + (k + 0) * 192 + hh];
                float wr1 = sm[S_WHH + (k + 1) * 192 + hh];
                float wr2 = sm[S_WHH + (k + 2) * 192 + hh];
                float wr3 = sm[S_WHH + (k + 3) * 192 + hh];
                float wz0 = sm[S_WHH + (k + 0) * 192 + 64 + hh];
                float wz1 = sm[S_WHH + (k + 1) * 192 + 64 + hh];
                float wz2 = sm[S_WHH + (k + 2) * 192 + 64 + hh];
                float wz3 = sm[S_WHH + (k + 3) * 192 + 64 + hh];
                float wn0 = sm[S_WHH + (k + 0) * 192 + 128 + hh];
                float wn1 = sm[S_WHH + (k + 1) * 192 + 128 + hh];
                float wn2 = sm[S_WHH + (k + 2) * 192 + 128 + hh];
                float wn3 = sm[S_WHH + (k + 3) * 192 + 128 + hh];
#pragma unroll
                for (int ci = 0; ci < 4; ci++){
                    int cl = cg + 8 * ci;
                    if (cl < c_n){
                        const float4 hv = *(const float4*)&sm[S_H + (c_lo + cl) * 64 + k];
                        aR[ci] += hv.x * wr0 + hv.y * wr1 + hv.z * wr2 + hv.w * wr3;
                        aZ[ci] += hv.x * wz0 + hv.y * wz1 + hv.z * wz2 + hv.w * wz3;
                        aN[ci] += hv.x * wn0 + hv.y * wn1 + hv.z * wn2 + hv.w * wn3;
                    }
                }
            }
            float2* hg2 = (float2*)(sm + S_HG2);
#pragma unroll
            for (int ci = 0; ci < 4; ci++){
                int cl = cg + 8 * ci;
                if (cl < c_n){
                    int c = c_lo + cl;
                    float xi = sm[S_X + c];
                    float r = fast_sigmoid(fmaf(xi, sm[S_UV + hh],       sm[S_UV + 192 + hh]) + aR[ci] + sm[S_BHH + hh]);
                    float z = fast_sigmoid(fmaf(xi, sm[S_UV + 64 + hh],  sm[S_UV + 256 + hh]) + aZ[ci] + sm[S_BHH + 64 + hh]);
                    float n = fast_tanh(   fmaf(xi, sm[S_UV + 128 + hh], sm[S_UV + 320 + hh]) + r * (aN[ci] + sm[S_BHH + 128 + hh]));
                    float hg = (1.f - z) * n + z * sm[S_H + c * 64 + hh];
                    sm[S_HGRU + c * 64 + hh] = hg;
                    st_peer(&sm[S_HGRU + c * 64 + hh], hg, peer);
                    hg2[cl * 68 + hh] = split_tf32(hg);
                }
            }
        }
        __syncthreads();

        // ---- Stage B: 6 sequential tensor-core MLP layers, all 16 warps ----
        mma_mlp<64,  0>(sm, S_HG2, 68,  S_BF2, 132, g_wk0, S_BIAS,       wid, lane, c_lo, c_n, peer); __syncthreads();
        mma_mlp<128, 0>(sm, S_BF2, 132, S_BF1, 132, g_wk1, S_BIAS + 128, wid, lane, c_lo, c_n, peer); __syncthreads();
        mma_mlp<128, 2>(sm, S_BF1, 132, S_B2,  0,   g_wk2, S_BIAS + 256, wid, lane, c_lo, c_n, peer); __syncthreads();
        mma_mlp<64,  0>(sm, S_HG2, 68,  S_BF2, 132, g_wq0, S_BIAS + 384, wid, lane, c_lo, c_n, peer); __syncthreads();
        mma_mlp<128, 0>(sm, S_BF2, 132, S_BF1, 132, g_wq1, S_BIAS + 512, wid, lane, c_lo, c_n, peer); __syncthreads();
        mma_mlp<128, 1>(sm, S_BF1, 132, S_QF,  0,   g_wq2, S_BIAS + 640, wid, lane, c_lo, c_n, peer);

        cluster_sync_();   // full KT + full hgru visible

        // ---- Stage C: transfer = q(QF) @ KT (4 row-slices/thread) ----
        {
            const int j = hh;
            if (j < kC){
                float acc[4];
#pragma unroll
                for (int i = 0; i < 4; i++) acc[i] = 0.f;
#pragma unroll 1
                for (int k = 0; k < 128; k += 4){
                    const float kv0 = sm[S_B2 + (k + 0) * 53 + j];
                    const float kv1 = sm[S_B2 + (k + 1) * 53 + j];
                    const float kv2 = sm[S_B2 + (k + 2) * 53 + j];
                    const float kv3 = sm[S_B2 + (k + 3) * 53 + j];
#pragma unroll
                    for (int ci = 0; ci < 4; ci++){
                        int cl = cg + 8 * ci;
                        if (cl < c_n){
                            const float4 qv = *(const float4*)&sm[S_QF + cl * 132 + k];
                            acc[ci] = fmaf(qv.x, kv0, fmaf(qv.y, kv1, fmaf(qv.z, kv2, fmaf(qv.w, kv3, acc[ci]))));
                        }
                    }
                }
#pragma unroll
                for (int ci = 0; ci < 4; ci++){
                    int cl = cg + 8 * ci;
                    if (cl < c_n) sm[S_TR + (c_lo + cl) * 56 + j] = acc[ci];
                }
            }
        }
        __syncthreads();

        // ---- norm ----
        {
            float p = 0.f;
            for (int idx = tid; idx < nloc; idx += kTH){
                int cc = c_lo + idx / 53, dd = idx % 53;
                float v = sm[S_TR + cc * 56 + dd];
                p = fmaf(v, v, p);
            }
#pragma unroll
            for (int o = 16; o; o >>= 1) p += __shfl_xor_sync(0xffffffffu, p, o);
            if ((tid & 31) == 0) sm[S_RED + wid] = p;
        }
        __syncthreads();
        if (tid == 0){
            float s = 0.f;
            for (int i = 0; i < 16; i++) s += sm[S_RED + i];
            sm[S_RED + 16] = s;
            st_peer(&sm[S_RED + 17], s, peer);
        }
        cluster_sync_();
        const float inv = rsqrtf(sm[S_RED + 16] + sm[S_RED + 17]);

        // ---- normalize + gate + emit mix + reg-FNC ----
        {
            float* mix_bt = out_mix + ((size_t)b * kT + t) * kC2;
            float* mixp_bt = g_mixp + ((size_t)b * kT + t) * kKP0;
#pragma unroll
            for (int j = 0; j < 3; j++){
                int idx = tid + j * kTH;
                if (idx < nloc){
                    int glob = c_lo * 53 + idx;
                    int cc = c_lo + idx / 53, dd = idx % 53;
                    float v = sm[S_TR + cc * 56 + dd] * inv;
                    float gate = fast_sigmoid(fabsf(v) + gbr[j]);
                    float val = v * gate;
                    sm[S_TR + cc * 56 + dd] = val;
                    mix_bt[glob] = val;
                    mixp_bt[glob] = __uint_as_float(cvt_tf32(val));
                    facc[j] += val;
                }
            }
        }
        __syncthreads();

        // ---- Stage D: h_new = transfer(own) @ hgru(full); write h fp32 + split ----
        {
            float acc[4];
#pragma unroll
            for (int i = 0; i < 4; i++) acc[i] = 0.f;
#pragma unroll 1
            for (int d = 0; d < 52; d += 4){
                float g0 = sm[S_HGRU + (d + 0) * 64 + hh];
                float g1 = sm[S_HGRU + (d + 1) * 64 + hh];
                float g2 = sm[S_HGRU + (d + 2) * 64 + hh];
                float g3 = sm[S_HGRU + (d + 3) * 64 + hh];
#pragma unroll
                for (int ci = 0; ci < 4; ci++){
                    int cl = cg + 8 * ci;
                    if (cl < c_n){
                        const float4 tv = *(const float4*)&sm[S_TR + (c_lo + cl) * 56 + d];
                        acc[ci] += tv.x * g0 + tv.y * g1 + tv.z * g2 + tv.w * g3;
                    }
                }
            }
            {
                float g = sm[S_HGRU + 52 * 64 + hh];
#pragma unroll
                for (int ci = 0; ci < 4; ci++){
                    int cl = cg + 8 * ci;
                    if (cl < c_n) acc[ci] += sm[S_TR + (c_lo + cl) * 56 + 52] * g;
                }
            }
            float2* hg2 = (float2*)(sm + S_HG2);
#pragma unroll
            for (int ci = 0; ci < 4; ci++){
                int cl = cg + 8 * ci;
                if (cl < c_n){
                    sm[S_H + (c_lo + cl) * 64 + hh] = acc[ci];
                    hg2[cl * 68 + hh] = split_tf32(acc[ci]);
                }
            }
        }
        __syncthreads();

        if (t < kT - 1 && tid < c_n){
            int c = c_lo + tid;
            float s2 = 0.f;
#pragma unroll
            for (int k = 0; k < 64; k += 4){
                const float4 hv = *(const float4*)&sm[S_H + c * 64 + k];
                s2 += hv.x * sm[S_PW + k] + hv.y * sm[S_PW + k + 1] + hv.z * sm[S_PW + k + 2] + hv.w * sm[S_PW + k + 3];
            }
            out_pred[((size_t)b * (kT - 1) + t) * kC + c] = s2 + predb;
        }

        cluster_sync_();
    }

#pragma unroll
    for (int j = 0; j < 3; j++){
        int idx = tid + j * kTH;
        if (idx < nloc)
            out_fnc[(size_t)b * kC2 + c_lo * 53 + idx] = facc[j] * (1.f / 256.f);
    }
}

// ---------------- tf32 tensor-core classifier GEMM ----------------
template<bool RELU, bool CVT>
__global__ __launch_bounds__(256, 2) void mma_gemm(const float* __restrict__ A, const float* __restrict__ B,
                                                   const float* __restrict__ bias, float* __restrict__ C,
                                                   int M, int Nstore, int Nreal, int K)
{
    extern __shared__ float smg[];
    float* As = smg;
    float* Bs = smg + 2 * 4608;

    const int tid = threadIdx.x;
    const int wid = tid >> 5, lane = tid & 31;
    const int warp_m = wid & 3, warp_n = wid >> 2;
    const int g = lane >> 2, l4 = lane & 3;
    const int bm = blockIdx.y * 128, bn = blockIdx.x * 128;

    const float* Ab = A + (size_t)bm * K;
    const float* Bb = B + (size_t)bn * K;

    float acc[2][8][4];
#pragma unroll
    for (int i = 0; i < 2; i++)
#pragma unroll
        for (int j = 0; j < 8; j++)
#pragma unroll
            for (int q = 0; q < 4; q++) acc[i][j][q] = 0.f;

    const int nk = K >> 5;

    auto load_tile = [&](int kt, int buf){
        const int k0 = kt * 32;
        float* as = As + buf * 4608;
        float* bs = Bs + buf * 4608;
#pragma unroll
        for (int i = 0; i < 4; i++){
            int ch = tid + i * 256;
            int row = ch >> 3;
            int ko = (ch & 7) * 4;
            cp_async16(&as[row * 36 + ko], Ab + (size_t)row * K + k0 + ko);
            cp_async16(&bs[row * 36 + ko], Bb + (size_t)row * K + k0 + ko);
        }
        asm volatile("cp.async.commit_group;" ::: "memory");
    };

    load_tile(0, 0);

    for (int kt = 0; kt < nk; kt++){
        const int buf = kt & 1;
        if (kt + 1 < nk){
            load_tile(kt + 1, buf ^ 1);
            asm volatile("cp.async.wait_group 1;" ::: "memory");
        } else {
            asm volatile("cp.async.wait_group 0;" ::: "memory");
        }
        __syncthreads();

        const float* as = As + buf * 4608;
        const float* bs = Bs + buf * 4608;
#pragma unroll
        for (int s = 0; s < 4; s++){
            const int kk = s * 8 + l4;
            uint32_t a[2][4], bf[8][2];
            const int r0 = warp_m * 32 + g;
            a[0][0] = __float_as_uint(as[(r0     ) * 36 + kk]);
            a[0][1] = __float_as_uint(as[(r0 +  8) * 36 + kk]);
            a[0][2] = __float_as_uint(as[(r0     ) * 36 + kk + 4]);
            a[0][3] = __float_as_uint(as[(r0 +  8) * 36 + kk + 4]);
            a[1][0] = __float_as_uint(as[(r0 + 16) * 36 + kk]);
            a[1][1] = __float_as_uint(as[(r0 + 24) * 36 + kk]);
            a[1][2] = __float_as_uint(as[(r0 + 16) * 36 + kk + 4]);
            a[1][3] = __float_as_uint(as[(r0 + 24) * 36 + kk + 4]);
#pragma unroll
            for (int nt = 0; nt < 8; nt++){
                const int nb = warp_n * 64 + nt * 8 + g;
                bf[nt][0] = __float_as_uint(bs[nb * 36 + kk]);
                bf[nt][1] = __float_as_uint(bs[nb * 36 + kk + 4]);
            }
#pragma unroll
            for (int mt = 0; mt < 2; mt++)
#pragma unroll
                for (int nt = 0; nt < 8; nt++)
                    mma_tf32(acc[mt][nt], a[mt], bf[nt]);
        }
        __syncthreads();
    }

#pragma unroll
    for (int mt = 0; mt < 2; mt++){
#pragma unroll
        for (int nt = 0; nt < 8; nt++){
            const int row = bm + warp_m * 32 + mt * 16 + g;
            const int col = bn + warp_n * 64 + nt * 8 + 2 * l4;
            const float b0v = (col < Nreal) ? bias[col] : 0.f;
            const float b1v = (col + 1 < Nreal) ? bias[col + 1] : 0.f;
            float v00 = acc[mt][nt][0] + b0v;
            float v01 = acc[mt][nt][1] + b1v;
            float v10 = acc[mt][nt][2] + b0v;
            float v11 = acc[mt][nt][3] + b1v;
            if (RELU){
                v00 = fmaxf(v00, 0.f); v01 = fmaxf(v01, 0.f);
                v10 = fmaxf(v10, 0.f); v11 = fmaxf(v11, 0.f);
            }
            if (CVT){
                v00 = __uint_as_float(cvt_tf32(v00)); v01 = __uint_as_float(cvt_tf32(v01));
                v10 = __uint_as_float(cvt_tf32(v10)); v11 = __uint_as_float(cvt_tf32(v11));
            }
            C[(size_t)row * Nstore + col]           = v00;
            C[(size_t)row * Nstore + col + 1]       = v01;
            C[(size_t)(row + 8) * Nstore + col]     = v10;
            C[(size_t)(row + 8) * Nstore + col + 1] = v11;
        }
    }
}

__global__ void zbar_kernel()
{
    const int b = blockIdx.x;
    for (int j = threadIdx.x; j < kN2; j += blockDim.x){
        float s = 0.f;
        for (int t = 0; t < kT; t++) s += g_z2[((size_t)b * kT + t) * kNP2 + j];
        g_zbar[b * kN2 + j] = s * (1.f / (float)kT);
    }
}

__global__ void logits_kernel(const float* __restrict__ w2, const float* __restrict__ b2, float* __restrict__ out)
{
    __shared__ float red[8];
    const int b = blockIdx.x >> 1, o = blockIdx.x & 1;
    float s = 0.f;
    for (int j = threadIdx.x; j < kN2; j += 256)
        s += g_zbar[b * kN2 + j] * w2[o * kN2 + j];
#pragma unroll
    for (int off = 16; off; off >>= 1) s += __shfl_xor_sync(0xffffffffu, s, off);
    if ((threadIdx.x & 31) == 0) red[threadIdx.x >> 5] = s;
    __syncthreads();
    if (threadIdx.x == 0){
        float t = 0.f;
        for (int i = 0; i < 8; i++) t += red[i];
        out[b * 2 + o] = t + b2[o];
    }
}

__global__ void xcopy_kernel(const float* __restrict__ x, float* __restrict__ outx)
{
    const int n = kB * (kT - 1) * kC;
    for (int idx = blockIdx.x * blockDim.x + threadIdx.x; idx < n; idx += gridDim.x * blockDim.x){
        int b = idx / ((kT - 1) * kC);
        int r = idx - b * (kT - 1) * kC;
        outx[idx] = x[(size_t)b * kT * kC + kC + r];
    }
}

extern "C" void kernel_launch(void* const* d_in, const int* in_sizes, int n_in,
                              void* d_out, int out_size)
{
    const float* x        = (const float*)d_in[0];
    const float* w_emb    = (const float*)d_in[1];
    const float* b_emb    = (const float*)d_in[2];
    const float* w_ih     = (const float*)d_in[3];
    const float* w_hh     = (const float*)d_in[4];
    const float* b_ih     = (const float*)d_in[5];
    const float* b_hh     = (const float*)d_in[6];
    const float* q_w0     = (const float*)d_in[7];
    const float* q_b0     = (const float*)d_in[8];
    const float* q_w1     = (const float*)d_in[9];
    const float* q_b1     = (const float*)d_in[10];
    const float* q_w2     = (const float*)d_in[11];
    const float* q_b2     = (const float*)d_in[12];
    const float* k_w0     = (const float*)d_in[13];
    const float* k_b0     = (const float*)d_in[14];
    const float* k_w1     = (const float*)d_in[15];
    const float* k_b1     = (const float*)d_in[16];
    const float* k_w2     = (const float*)d_in[17];
    const float* k_b2     = (const float*)d_in[18];
    const float* gate_bias= (const float*)d_in[19];
    const float* pred_w   = (const float*)d_in[20];
    const float* pred_b   = (const float*)d_in[21];
    const float* clf_w0   = (const float*)d_in[22];
    const float* clf_b0   = (const float*)d_in[23];
    const float* clf_w1   = (const float*)d_in[24];
    const float* clf_b1   = (const float*)d_in[25];
    const float* clf_w2   = (const float*)d_in[26];
    const float* clf_b2   = (const float*)d_in[27];

    float* out      = (float*)d_out;
    float* out_log  = out;
    float* out_fnc  = out + 2 * kB;
    float* out_mix  = out_fnc + (size_t)kB * kC2;
    float* out_pred = out_mix + (size_t)kB * kT * kC2;
    float* out_x    = out_pred + (size_t)kB * (kT - 1) * kC;

    cudaFuncSetAttribute(recurrent_kernel, cudaFuncAttributeMaxDynamicSharedMemorySize, SM_BYTES);
    cudaFuncSetAttribute(mma_gemm<true, true>,  cudaFuncAttributeMaxDynamicSharedMemorySize, 2 * 2 * 4608 * 4);
    cudaFuncSetAttribute(mma_gemm<true, false>, cudaFuncAttributeMaxDynamicSharedMemorySize, 2 * 2 * 4608 * 4);

    prep_small<<<48, 256>>>(w_ih, w_emb, b_emb, b_ih, w_hh);
    prep_frag<<<32, 256>>>(q_w0, q_w1, q_w2, k_w0, k_w1, k_w2);
    pack_clf<<<2048, 256>>>(clf_w0, clf_w1);

    recurrent_kernel<<<2 * kB, kTH, SM_BYTES>>>(x, b_hh, q_b0, q_b1, q_b2, k_b0, k_b1, k_b2,
                                                gate_bias, pred_w, pred_b,
                                                out_mix, out_fnc, out_pred);

    float *pz1, *pz2, *pw0p, *pw1p, *pmixp;
    cudaGetSymbolAddress((void**)&pz1,   g_z1);
    cudaGetSymbolAddress((void**)&pz2,   g_z2);
    cudaGetSymbolAddress((void**)&pw0p,  g_w0p);
    cudaGetSymbolAddress((void**)&pw1p,  g_w1p);
    cudaGetSymbolAddress((void**)&pmixp, g_mixp);

    const int smem_gemm = 2 * 2 * 4608 * 4;
    mma_gemm<true, true ><<<dim3(kNP1 / 128, kM / 128), 256, smem_gemm>>>(pmixp, pw0p, clf_b0, pz1, kM, kNP1, kN1, kKP0);
    mma_gemm<true, false><<<dim3(kNP2 / 128, kM / 128), 256, smem_gemm>>>(pz1,   pw1p, clf_b1, pz2, kM, kNP2, kN2, kNP1);

    zbar_kernel<<<kB, 256>>>();
    logits_kernel<<<2 * kB, 256>>>(clf_w2, clf_b2, out_log);
    xcopy_kernel<<<512, 256>>>(x, out_x);
}

// round 17
// speedup vs baseline: 1.1026x; 1.0414x over previous
#include <cuda_runtime.h>
#include <math.h>
#include <stdint.h>

static inline int cdiv(int a, int b){ return (a + b - 1) / b; }

constexpr int kB = 64, kT = 256, kC = 53, kH = 64, kA = 128;
constexpr int kC2 = kC * kC;
constexpr int kN1 = kC2 / 2;
constexpr int kN2 = kC2 / 4;
constexpr int kM  = kB * kT;
constexpr int kKP0 = 2816, kNP1 = 1408, kNP2 = 768;
constexpr int kTH = 512;

__device__ float g_u[192], g_v[192];
__device__ float g_whht[64 * 192];
__device__ float4 g_wq0[4096], g_wq1[8192], g_wq2[8192];
__device__ float4 g_wk0[4096], g_wk1[8192], g_wk2[8192];
__device__ float g_mixp[(size_t)kM * kKP0];
__device__ float g_w0p[(size_t)kNP1 * kKP0];
__device__ float g_w1p[(size_t)kNP2 * kNP1];
__device__ float g_z1[(size_t)kM * kNP1];
__device__ float g_z2[(size_t)kM * kNP2];
__device__ float g_zbar[kB * kN2];

__device__ __forceinline__ float fast_sigmoid(float x){
    float e; asm("ex2.approx.f32 %0, %1;" : "=f"(e) : "f"(-x * 1.4426950408889634f));
    float r; asm("rcp.approx.f32 %0, %1;" : "=f"(r) : "f"(1.f + e));
    return r;
}
__device__ __forceinline__ float fast_tanh(float x){ return fmaf(2.f, fast_sigmoid(2.f * x), -1.f); }
__device__ __forceinline__ uint32_t cvt_tf32(float x){
    uint32_t y; asm("cvt.rna.tf32.f32 %0, %1;" : "=r"(y) : "f"(x)); return y;
}
__device__ __forceinline__ float2 split_tf32(float v){
    float hi = __uint_as_float(cvt_tf32(v));
    float lo = __uint_as_float(cvt_tf32(v - hi));
    return make_float2(hi, lo);
}
__device__ __forceinline__ void st_peer(float* p, float v, uint32_t peer){
    uint32_t l = (uint32_t)__cvta_generic_to_shared(p);
    uint32_t r; asm("mapa.shared::cluster.u32 %0, %1, %2;" : "=r"(r) : "r"(l), "r"(peer));
    asm volatile("st.shared::cluster.f32 [%0], %1;" :: "r"(r), "f"(v) : "memory");
}
__device__ __forceinline__ void cluster_sync_(){
    asm volatile("barrier.cluster.arrive.aligned;" ::: "memory");
    asm volatile("barrier.cluster.wait.aligned;" ::: "memory");
}
__device__ __forceinline__ void cp_async16(void* smem, const void* gmem){
    uint32_t s = (uint32_t)__cvta_generic_to_shared(smem);
    asm volatile("cp.async.cg.shared.global [%0], [%1], 16;" :: "r"(s), "l"(gmem) : "memory");
}
__device__ __forceinline__ void mma_tf32(float* c, const uint32_t* a, const uint32_t* b){
    asm volatile("mma.sync.aligned.m16n8k8.row.col.f32.tf32.tf32.f32 "
        "{%0,%1,%2,%3}, {%4,%5,%6,%7}, {%8,%9}, {%0,%1,%2,%3};"
        : "+f"(c[0]), "+f"(c[1]), "+f"(c[2]), "+f"(c[3])
        : "r"(a[0]), "r"(a[1]), "r"(a[2]), "r"(a[3]), "r"(b[0]), "r"(b[1]));
}

// ---- cluster mbarrier handshake helpers ----
__device__ __forceinline__ void mbar_init(float* p, uint32_t count){
    uint32_t a = (uint32_t)__cvta_generic_to_shared(p);
    asm volatile("mbarrier.init.shared.b64 [%0], %1;" :: "r"(a), "r"(count) : "memory");
}
__device__ __forceinline__ void mbar_arrive_both(float* p, uint32_t peer){
    uint32_t l = (uint32_t)__cvta_generic_to_shared(p);
    uint32_t r; asm("mapa.shared::cluster.u32 %0, %1, %2;" : "=r"(r) : "r"(l), "r"(peer));
    asm volatile("mbarrier.arrive.shared.b64 _, [%0];" :: "r"(l) : "memory");
    asm volatile("mbarrier.arrive.shared::cluster.b64 _, [%0];" :: "r"(r) : "memory");
}
__device__ __forceinline__ void mbar_wait(float* p, uint32_t parity){
    uint32_t l = (uint32_t)__cvta_generic_to_shared(p);
    asm volatile(
        "{\n\t"
        ".reg .pred P1;\n\t"
        "WL_%=:\n\t"
        "mbarrier.try_wait.parity.acquire.cluster.shared::cta.b64 P1, [%0], %1;\n\t"
        "@P1 bra.uni WD_%=;\n\t"
        "bra.uni WL_%=;\n\t"
        "WD_%=:\n\t"
        "}" :: "r"(l), "r"(parity) : "memory");
}

__global__ void prep_small(const float* __restrict__ w_ih, const float* __restrict__ w_emb,
                           const float* __restrict__ b_emb, const float* __restrict__ b_ih,
                           const float* __restrict__ w_hh)
{
    int gt = blockIdx.x * blockDim.x + threadIdx.x;
    int gs = gridDim.x * blockDim.x;
    for (int j = gt; j < 192; j += gs){
        float su = 0.f, sv = 0.f;
        for (int e = 0; e < 64; e++){
            su += w_ih[j * 64 + e] * w_emb[e];
            sv += w_ih[j * 64 + e] * b_emb[e];
        }
        g_u[j] = su; g_v[j] = sv + b_ih[j];
    }
    for (int idx = gt; idx < 64 * 192; idx += gs){
        int k = idx / 192, j = idx - k * 192;
        g_whht[idx] = w_hh[j * 64 + k];
    }
}

__device__ __forceinline__ void bake_one(float4* dst, const float* W, int K, int idx){
    int kc = idx >> 10, rem = idx & 1023;
    int wn = rem >> 8, r2 = rem & 255;
    int grp = r2 >> 5, lane = r2 & 31;
    int ks = grp >> 2, nt = grp & 3;
    int n = wn * 32 + nt * 8 + (lane >> 2);
    int k = kc * 16 + ks * 8 + (lane & 3);
    float v0 = W[n * K + k], v1 = W[n * K + k + 4];
    float h0 = __uint_as_float(cvt_tf32(v0));
    float h1 = __uint_as_float(cvt_tf32(v1));
    dst[idx] = make_float4(h0, __uint_as_float(cvt_tf32(v0 - h0)),
                           h1, __uint_as_float(cvt_tf32(v1 - h1)));
}

__global__ void prep_frag(const float* __restrict__ qw0, const float* __restrict__ qw1, const float* __restrict__ qw2,
                          const float* __restrict__ kw0, const float* __restrict__ kw1, const float* __restrict__ kw2)
{
    int gt = blockIdx.x * blockDim.x + threadIdx.x;
    int gs = gridDim.x * blockDim.x;
    for (int i = gt; i < 4096; i += gs){ bake_one(g_wq0, qw0, 64, i); bake_one(g_wk0, kw0, 64, i); }
    for (int i = gt; i < 8192; i += gs){
        bake_one(g_wq1, qw1, 128, i); bake_one(g_wq2, qw2, 128, i);
        bake_one(g_wk1, kw1, 128, i); bake_one(g_wk2, kw2, 128, i);
    }
}

__global__ void pack_clf(const float* __restrict__ clf_w0, const float* __restrict__ clf_w1)
{
    size_t gt = (size_t)blockIdx.x * blockDim.x + threadIdx.x;
    size_t gs = (size_t)gridDim.x * blockDim.x;
    for (size_t idx = gt; idx < (size_t)kNP1 * kKP0; idx += gs){
        int j = (int)(idx / kKP0), k = (int)(idx - (size_t)j * kKP0);
        float v = (j < kN1 && k < kC2) ? clf_w0[(size_t)j * kC2 + k] : 0.f;
        g_w0p[idx] = __uint_as_float(cvt_tf32(v));
    }
    for (size_t idx = gt; idx < (size_t)kNP2 * kNP1; idx += gs){
        int j = (int)(idx / kNP1), k = (int)(idx - (size_t)j * kNP1);
        float v = (j < kN2 && k < kN1) ? clf_w1[(size_t)j * kN1 + k] : 0.f;
        g_w1p[idx] = __uint_as_float(cvt_tf32(v));
    }
}

// ---------------- smem layout (floats) ----------------
constexpr int S_H    = 0;
constexpr int S_HGRU = S_H + kC * kH;
constexpr int S_B2   = S_HGRU + kC * kH;         // KT 128*53 full (peer pushed)
constexpr int S_QF   = S_B2 + 128 * 53;          // q fp32 32*132
constexpr int S_TR   = S_QF + 32 * 132;          // 53*56
constexpr int S_WHH  = S_TR + kC * 56;           // 64*192
constexpr int S_UV   = S_WHH + 64 * 192;         // 384
constexpr int S_BHH  = S_UV + 384;               // 192
constexpr int S_PW   = S_BHH + 192;              // 64
constexpr int S_X    = S_PW + 64;                // 56
constexpr int S_RED  = S_X + 56;                 // 24
constexpr int S_MB   = ((S_RED + 24) + 1) & ~1;  // 2 mbarriers (4 floats, 8B-aligned)
constexpr int S_BIAS = S_MB + 4;                 // 6*128
constexpr int S_HG2  = S_BIAS + 768;             // 32*68 float2
constexpr int S_BF1  = S_HG2 + 4352;             // 32*132 float2
constexpr int S_BF2  = S_BF1 + 8448;
constexpr int SM_FLOATS = S_BF2 + 8448;
constexpr int SM_BYTES  = SM_FLOATS * 4;

// 16-warp tensor-core MLP (R13 geometry), 3xTF32.
template<int K, int OUTMODE>
__device__ __forceinline__ void mma_mlp(float* __restrict__ sm, int inOff, int Sin, int outOff, int Sout,
                                        const float4* __restrict__ gw, int biasOff,
                                        int wid, int lane, int c_lo, int c_n, uint32_t peer)
{
    const int warp_m = wid & 1, warp_n = wid >> 1;
    const int wn32 = warp_n >> 1, ntbase = (warp_n & 1) * 2;
    const int g = lane >> 2, l4 = lane & 3;
    constexpr int NC = K / 16;
    const float2* in2 = (const float2*)(sm + inOff);

    float acc[2][4];
#pragma unroll
    for (int i = 0; i < 2; i++)
#pragma unroll
        for (int j = 0; j < 4; j++) acc[i][j] = 0.f;

    float4 bb[2][4];
#pragma unroll
    for (int ks2 = 0; ks2 < 2; ks2++)
#pragma unroll
        for (int nt = 0; nt < 2; nt++)
            bb[0][ks2 * 2 + nt] = gw[wn32 * 256 + (ks2 * 4 + ntbase + nt) * 32 + lane];

    const int r0 = warp_m * 16 + g;
#pragma unroll 2
    for (int kc = 0; kc < NC; kc++){
        const int cur = kc & 1;
        if (kc + 1 < NC){
#pragma unroll
            for (int ks2 = 0; ks2 < 2; ks2++)
#pragma unroll
                for (int nt = 0; nt < 2; nt++)
                    bb[cur ^ 1][ks2 * 2 + nt] = gw[((kc + 1) * 4 + wn32) * 256 + (ks2 * 4 + ntbase + nt) * 32 + lane];
        }
#pragma unroll
        for (int ks = 0; ks < 2; ks++){
            const int kk = kc * 16 + ks * 8 + l4;
            float2 a0 = in2[r0 * Sin + kk];
            float2 a1 = in2[(r0 + 8) * Sin + kk];
            float2 a2 = in2[r0 * Sin + kk + 4];
            float2 a3 = in2[(r0 + 8) * Sin + kk + 4];
            uint32_t ahi[4] = {__float_as_uint(a0.x), __float_as_uint(a1.x), __float_as_uint(a2.x), __float_as_uint(a3.x)};
            uint32_t alo[4] = {__float_as_uint(a0.y), __float_as_uint(a1.y), __float_as_uint(a2.y), __float_as_uint(a3.y)};
#pragma unroll
            for (int nt = 0; nt < 2; nt++){
                float4 w = bb[cur][ks * 2 + nt];
                uint32_t bhi[2] = {__float_as_uint(w.x), __float_as_uint(w.z)};
                uint32_t blo[2] = {__float_as_uint(w.y), __float_as_uint(w.w)};
                mma_tf32(acc[nt], ahi, bhi);
                mma_tf32(acc[nt], ahi, blo);
                mma_tf32(acc[nt], alo, bhi);
            }
        }
    }

    const float* sbias = sm + biasOff;
    const int row0 = r0, row1 = r0 + 8;
    const bool ok0 = row0 < c_n, ok1 = row1 < c_n;
#pragma unroll
    for (int nt = 0; nt < 2; nt++){
        const int n0 = warp_n * 16 + nt * 8 + 2 * l4;
        const float b0 = sbias[n0], b1 = sbias[n0 + 1];
        float v00 = acc[nt][0] + b0, v01 = acc[nt][1] + b1;
        float v10 = acc[nt][2] + b0, v11 = acc[nt][3] + b1;
        if (OUTMODE == 0){
            v00 = fmaxf(v00, 0.f); v01 = fmaxf(v01, 0.f);
            v10 = fmaxf(v10, 0.f); v11 = fmaxf(v11, 0.f);
            float2* o2 = (float2*)(sm + outOff);
            if (ok0){ o2[row0 * Sout + n0] = split_tf32(v00); o2[row0 * Sout + n0 + 1] = split_tf32(v01); }
            if (ok1){ o2[row1 * Sout + n0] = split_tf32(v10); o2[row1 * Sout + n0 + 1] = split_tf32(v11); }
        } else if (OUTMODE == 1){
            float* oq = sm + outOff;
            if (ok0){ oq[row0 * 132 + n0] = v00; oq[row0 * 132 + n0 + 1] = v01; }
            if (ok1){ oq[row1 * 132 + n0] = v10; oq[row1 * 132 + n0 + 1] = v11; }
        } else {
            float* kt = sm + outOff;
            if (ok0){
                int c = c_lo + row0;
                kt[n0 * 53 + c] = v00;       st_peer(&kt[n0 * 53 + c], v00, peer);
                kt[(n0 + 1) * 53 + c] = v01; st_peer(&kt[(n0 + 1) * 53 + c], v01, peer);
            }
            if (ok1){
                int c = c_lo + row1;
                kt[n0 * 53 + c] = v10;       st_peer(&kt[n0 * 53 + c], v10, peer);
                kt[(n0 + 1) * 53 + c] = v11; st_peer(&kt[(n0 + 1) * 53 + c], v11, peer);
            }
        }
    }
}

__global__ void __cluster_dims__(2, 1, 1) __launch_bounds__(kTH, 1)
recurrent_kernel(const float* __restrict__ x,
                 const float* __restrict__ b_hh,
                 const float* __restrict__ qb0, const float* __restrict__ qb1, const float* __restrict__ qb2,
                 const float* __restrict__ kb0, const float* __restrict__ kb1, const float* __restrict__ kb2,
                 const float* __restrict__ gate_bias,
                 const float* __restrict__ pred_w, const float* __restrict__ pred_b,
                 float* __restrict__ out_mix, float* __restrict__ out_fnc, float* __restrict__ out_pred)
{
    extern __shared__ float sm[];
    const int tid = threadIdx.x;
    const int b = blockIdx.x >> 1;
    const uint32_t rank = blockIdx.x & 1;
    const uint32_t peer = rank ^ 1;
    const int c_lo = rank ? 27 : 0;
    const int c_n  = rank ? 26 : 27;

    for (int i = tid; i < kC * kH; i += kTH) sm[S_H + i] = 0.f;
    for (int i = tid; i < 64 * 192; i += kTH) sm[S_WHH + i] = g_whht[i];
    for (int i = tid; i < SM_FLOATS - S_HG2; i += kTH) sm[S_HG2 + i] = 0.f;
    if (tid < 192){ sm[S_UV + tid] = g_u[tid]; sm[S_UV + 192 + tid] = g_v[tid]; sm[S_BHH + tid] = b_hh[tid]; }
    if (tid < 64) sm[S_PW + tid] = pred_w[tid];
    if (tid < 128){
        sm[S_BIAS + tid]       = kb0[tid];
        sm[S_BIAS + 128 + tid] = kb1[tid];
        sm[S_BIAS + 256 + tid] = kb2[tid];
        sm[S_BIAS + 384 + tid] = qb0[tid];
        sm[S_BIAS + 512 + tid] = qb1[tid];
        sm[S_BIAS + 640 + tid] = qb2[tid];
    }
    if (tid == 0){
        mbar_init(sm + S_MB, 2);       // norm handshake
        mbar_init(sm + S_MB + 2, 2);   // end-of-step handshake
    }
    const float predb = pred_b[0];
    __syncthreads();

    const int hh = tid & 63, cg = tid >> 6;
    const int lane = tid & 31, wid = tid >> 5;
    const int nloc = c_n * 53;

    float facc[3], gbr[3];
#pragma unroll
    for (int j = 0; j < 3; j++){
        facc[j] = 0.f;
        int idx = tid + j * kTH;
        gbr[j] = (idx < nloc) ? gate_bias[c_lo * 53 + idx] : 0.f;
    }

    float xr = (tid < kC) ? x[((size_t)b * kT) * kC + tid] : 0.f;

    cluster_sync_();   // mbarriers initialized everywhere

    for (int t = 0; t < kT; t++){
        const uint32_t par = t & 1;
        if (tid < kC) sm[S_X + tid] = xr;
        __syncthreads();
        {
            int tn = (t + 1 < kT) ? t + 1 : t;
            if (tid < kC) xr = x[((size_t)b * kT + tn) * kC + tid];
        }

        // ---- Stage A: GRU own rows; hgru fp32 (own+peer) + split ----
        {
            float aR[4], aZ[4], aN[4];
#pragma unroll
            for (int i = 0; i < 4; i++){ aR[i] = 0.f; aZ[i] = 0.f; aN[i] = 0.f; }
#pragma unroll 1
            for (int k = 0; k < 64; k += 4){
                float wr0 = sm[S_WHH + (k + 0) * 192 + hh];
                float wr1 = sm[S_WHH + (k + 1) * 192 + hh];
                float wr2 = sm[S_WHH + (k + 2) * 192 + hh];
                float wr3 = sm[S_WHH + (k + 3) * 192 + hh];
                float wz0 = sm[S_WHH + (k + 0) * 192 + 64 + hh];
                float wz1 = sm[S_WHH + (k + 1) * 192 + 64 + hh];
                float wz2 = sm[S_WHH + (k + 2) * 192 + 64 + hh];
                float wz3 = sm[S_WHH + (k + 3) * 192 + 64 + hh];
                float wn0 = sm[S_WHH + (k + 0) * 192 + 128 + hh];
                float wn1 = sm[S_WHH + (k + 1) * 192 + 128 + hh];
                float wn2 = sm[S_WHH + (k + 2) * 192 + 128 + hh];
                float wn3 = sm[S_WHH + (k + 3) * 192 + 128 + hh];
#pragma unroll
                for (int ci = 0; ci < 4; ci++){
                    int cl = cg + 8 * ci;
                    if (cl < c_n){
                        const float4 hv = *(const float4*)&sm[S_H + (c_lo + cl) * 64 + k];
                        aR[ci] += hv.x * wr0 + hv.y * wr1 + hv.z * wr2 + hv.w * wr3;
                        aZ[ci] += hv.x * wz0 + hv.y * wz1 + hv.z * wz2 + hv.w * wz3;
                        aN[ci] += hv.x * wn0 + hv.y * wn1 + hv.z * wn2 + hv.w * wn3;
                    }
                }
            }
            float2* hg2 = (float2*)(sm + S_HG2);
#pragma unroll
            for (int ci = 0; ci < 4; ci++){
                int cl = cg + 8 * ci;
                if (cl < c_n){
                    int c = c_lo + cl;
                    float xi = sm[S_X + c];
                    float r = fast_sigmoid(fmaf(xi, sm[S_UV + hh],       sm[S_UV + 192 + hh]) + aR[ci] + sm[S_BHH + hh]);
                    float z = fast_sigmoid(fmaf(xi, sm[S_UV + 64 + hh],  sm[S_UV + 256 + hh]) + aZ[ci] + sm[S_BHH + 64 + hh]);
                    float n = fast_tanh(   fmaf(xi, sm[S_UV + 128 + hh], sm[S_UV + 320 + hh]) + r * (aN[ci] + sm[S_BHH + 128 + hh]));
                    float hg = (1.f - z) * n + z * sm[S_H + c * 64 + hh];
                    sm[S_HGRU + c * 64 + hh] = hg;
                    st_peer(&sm[S_HGRU + c * 64 + hh], hg, peer);
                    hg2[cl * 68 + hh] = split_tf32(hg);
                }
            }
        }
        __syncthreads();

        // ---- Stage B: 6 tensor-core MLP layers (k2->q0 sync removed) ----
        mma_mlp<64,  0>(sm, S_HG2, 68,  S_BF2, 132, g_wk0, S_BIAS,       wid, lane, c_lo, c_n, peer); __syncthreads();
        mma_mlp<128, 0>(sm, S_BF2, 132, S_BF1, 132, g_wk1, S_BIAS + 128, wid, lane, c_lo, c_n, peer); __syncthreads();
        mma_mlp<128, 2>(sm, S_BF1, 132, S_B2,  0,   g_wk2, S_BIAS + 256, wid, lane, c_lo, c_n, peer);
        mma_mlp<64,  0>(sm, S_HG2, 68,  S_BF2, 132, g_wq0, S_BIAS + 384, wid, lane, c_lo, c_n, peer); __syncthreads();
        mma_mlp<128, 0>(sm, S_BF2, 132, S_BF1, 132, g_wq1, S_BIAS + 512, wid, lane, c_lo, c_n, peer); __syncthreads();
        mma_mlp<128, 1>(sm, S_BF1, 132, S_QF,  0,   g_wq2, S_BIAS + 640, wid, lane, c_lo, c_n, peer);

        cluster_sync_();   // heavy fence: full KT + hgru DSMEM pushes visible

        // ---- Stage C: transfer = q(QF) @ KT ----
        {
            const int j = hh;
            if (j < kC){
                float acc[4];
#pragma unroll
                for (int i = 0; i < 4; i++) acc[i] = 0.f;
#pragma unroll 1
                for (int k = 0; k < 128; k += 4){
                    const float kv0 = sm[S_B2 + (k + 0) * 53 + j];
                    const float kv1 = sm[S_B2 + (k + 1) * 53 + j];
                    const float kv2 = sm[S_B2 + (k + 2) * 53 + j];
                    const float kv3 = sm[S_B2 + (k + 3) * 53 + j];
#pragma unroll
                    for (int ci = 0; ci < 4; ci++){
                        int cl = cg + 8 * ci;
                        if (cl < c_n){
                            const float4 qv = *(const float4*)&sm[S_QF + cl * 132 + k];
                            acc[ci] = fmaf(qv.x, kv0, fmaf(qv.y, kv1, fmaf(qv.z, kv2, fmaf(qv.w, kv3, acc[ci]))));
                        }
                    }
                }
#pragma unroll
                for (int ci = 0; ci < 4; ci++){
                    int cl = cg + 8 * ci;
                    if (cl < c_n) sm[S_TR + (c_lo + cl) * 56 + j] = acc[ci];
                }
            }
        }
        __syncthreads();

        // ---- norm: partial, exchange via mbarrier handshake ----
        {
            float p = 0.f;
            for (int idx = tid; idx < nloc; idx += kTH){
                int cc = c_lo + idx / 53, dd = idx % 53;
                float v = sm[S_TR + cc * 56 + dd];
                p = fmaf(v, v, p);
            }
#pragma unroll
            for (int o = 16; o; o >>= 1) p += __shfl_xor_sync(0xffffffffu, p, o);
            if ((tid & 31) == 0) sm[S_RED + wid] = p;
        }
        __syncthreads();
        if (tid == 0){
            float s = 0.f;
            for (int i = 0; i < 16; i++) s += sm[S_RED + i];
            sm[S_RED + 16] = s;
            st_peer(&sm[S_RED + 17], s, peer);
            mbar_arrive_both(sm + S_MB, peer);
        }
        mbar_wait(sm + S_MB, par);
        const float inv = rsqrtf(sm[S_RED + 16] + sm[S_RED + 17]);

        // ---- normalize + gate + emit mix + reg-FNC ----
        {
            float* mix_bt = out_mix + ((size_t)b * kT + t) * kC2;
            float* mixp_bt = g_mixp + ((size_t)b * kT + t) * kKP0;
#pragma unroll
            for (int j = 0; j < 3; j++){
                int idx = tid + j * kTH;
                if (idx < nloc){
                    int glob = c_lo * 53 + idx;
                    int cc = c_lo + idx / 53, dd = idx % 53;
                    float v = sm[S_TR + cc * 56 + dd] * inv;
                    float gate = fast_sigmoid(fabsf(v) + gbr[j]);
                    float val = v * gate;
                    sm[S_TR + cc * 56 + dd] = val;
                    mix_bt[glob] = val;
                    mixp_bt[glob] = __uint_as_float(cvt_tf32(val));
                    facc[j] += val;
                }
            }
        }
        __syncthreads();

        // ---- Stage D: h_new = transfer(own) @ hgru(full); write h fp32 + split ----
        {
            float acc[4];
#pragma unroll
            for (int i = 0; i < 4; i++) acc[i] = 0.f;
#pragma unroll 1
            for (int d = 0; d < 52; d += 4){
                float g0 = sm[S_HGRU + (d + 0) * 64 + hh];
                float g1 = sm[S_HGRU + (d + 1) * 64 + hh];
                float g2 = sm[S_HGRU + (d + 2) * 64 + hh];
                float g3 = sm[S_HGRU + (d + 3) * 64 + hh];
#pragma unroll
                for (int ci = 0; ci < 4; ci++){
                    int cl = cg + 8 * ci;
                    if (cl < c_n){
                        const float4 tv = *(const float4*)&sm[S_TR + (c_lo + cl) * 56 + d];
                        acc[ci] += tv.x * g0 + tv.y * g1 + tv.z * g2 + tv.w * g3;
                    }
                }
            }
            {
                float g = sm[S_HGRU + 52 * 64 + hh];
#pragma unroll
                for (int ci = 0; ci < 4; ci++){
                    int cl = cg + 8 * ci;
                    if (cl < c_n) acc[ci] += sm[S_TR + (c_lo + cl) * 56 + 52] * g;
                }
            }
            float2* hg2 = (float2*)(sm + S_HG2);
#pragma unroll
            for (int ci = 0; ci < 4; ci++){
                int cl = cg + 8 * ci;
                if (cl < c_n){
                    sm[S_H + (c_lo + cl) * 64 + hh] = acc[ci];
                    hg2[cl * 68 + hh] = split_tf32(acc[ci]);
                }
            }
        }
        __syncthreads();

        if (t < kT - 1 && tid < c_n){
            int c = c_lo + tid;
            float s2 = 0.f;
#pragma unroll
            for (int k = 0; k < 64; k += 4){
                const float4 hv = *(const float4*)&sm[S_H + c * 64 + k];
                s2 += hv.x * sm[S_PW + k] + hv.y * sm[S_PW + k + 1] + hv.z * sm[S_PW + k + 2] + hv.w * sm[S_PW + k + 3];
            }
            out_pred[((size_t)b * (kT - 1) + t) * kC + c] = s2 + predb;
        }

        // ---- end-of-step rendezvous via mbarrier ----
        __syncthreads();
        if (tid == 0) mbar_arrive_both(sm + S_MB + 2, peer);
        mbar_wait(sm + S_MB + 2, par);
    }

#pragma unroll
    for (int j = 0; j < 3; j++){
        int idx = tid + j * kTH;
        if (idx < nloc)
            out_fnc[(size_t)b * kC2 + c_lo * 53 + idx] = facc[j] * (1.f / 256.f);
    }
}

// ---------------- tf32 classifier GEMM: 3-stage cp.async, 1 sync/iter ----------------
template<bool RELU, bool CVT>
__global__ __launch_bounds__(256, 2) void mma_gemm(const float* __restrict__ A, const float* __restrict__ B,
                                                   const float* __restrict__ bias, float* __restrict__ C,
                                                   int M, int Nstore, int Nreal, int K)
{
    extern __shared__ float smg[];
    float* As = smg;                 // 3 x 128 x 36
    float* Bs = smg + 3 * 4608;      // 3 x 128 x 36

    const int tid = threadIdx.x;
    const int wid = tid >> 5, lane = tid & 31;
    const int warp_m = wid & 3, warp_n = wid >> 2;
    const int g = lane >> 2, l4 = lane & 3;
    const int bm = blockIdx.y * 128, bn = blockIdx.x * 128;

    const float* Ab = A + (size_t)bm * K;
    const float* Bb = B + (size_t)bn * K;

    float acc[2][8][4];
#pragma unroll
    for (int i = 0; i < 2; i++)
#pragma unroll
        for (int j = 0; j < 8; j++)
#pragma unroll
            for (int q = 0; q < 4; q++) acc[i][j][q] = 0.f;

    const int nk = K >> 5;

    auto load_tile = [&](int kt, int buf){
        const int k0 = kt * 32;
        float* as = As + buf * 4608;
        float* bs = Bs + buf * 4608;
#pragma unroll
        for (int i = 0; i < 4; i++){
            int ch = tid + i * 256;
            int row = ch >> 3;
            int ko = (ch & 7) * 4;
            cp_async16(&as[row * 36 + ko], Ab + (size_t)row * K + k0 + ko);
            cp_async16(&bs[row * 36 + ko], Bb + (size_t)row * K + k0 + ko);
        }
        asm volatile("cp.async.commit_group;" ::: "memory");
    };

    load_tile(0, 0);
    if (nk > 1) load_tile(1, 1);

    for (int kt = 0; kt < nk; kt++){
        const int buf = kt % 3;
        if (kt + 1 < nk){
            asm volatile("cp.async.wait_group 1;" ::: "memory");
        } else {
            asm volatile("cp.async.wait_group 0;" ::: "memory");
        }
        __syncthreads();
        if (kt + 2 < nk) load_tile(kt + 2, (kt + 2) % 3);

        const float* as = As + buf * 4608;
        const float* bs = Bs + buf * 4608;
#pragma unroll
        for (int s = 0; s < 4; s++){
            const int kk = s * 8 + l4;
            uint32_t a[2][4], bf[8][2];
            const int r0 = warp_m * 32 + g;
            a[0][0] = __float_as_uint(as[(r0     ) * 36 + kk]);
            a[0][1] = __float_as_uint(as[(r0 +  8) * 36 + kk]);
            a[0][2] = __float_as_uint(as[(r0     ) * 36 + kk + 4]);
            a[0][3] = __float_as_uint(as[(r0 +  8) * 36 + kk + 4]);
            a[1][0] = __float_as_uint(as[(r0 + 16) * 36 + kk]);
            a[1][1] = __float_as_uint(as[(r0 + 24) * 36 + kk]);
            a[1][2] = __float_as_uint(as[(r0 + 16) * 36 + kk + 4]);
            a[1][3] = __float_as_uint(as[(r0 + 24) * 36 + kk + 4]);
#pragma unroll
            for (int nt = 0; nt < 8; nt++){
                const int nb = warp_n * 64 + nt * 8 + g;
                bf[nt][0] = __float_as_uint(bs[nb * 36 + kk]);
                bf[nt][1] = __float_as_uint(bs[nb * 36 + kk + 4]);
            }
#pragma unroll
            for (int mt = 0; mt < 2; mt++)
#pragma unroll
                for (int nt = 0; nt < 8; nt++)
                    mma_tf32(acc[mt][nt], a[mt], bf[nt]);
        }
    }

#pragma unroll
    for (int mt = 0; mt < 2; mt++){
#pragma unroll
        for (int nt = 0; nt < 8; nt++){
            const int row = bm + warp_m * 32 + mt * 16 + g;
            const int col = bn + warp_n * 64 + nt * 8 + 2 * l4;
            const float b0v = (col < Nreal) ? bias[col] : 0.f;
            const float b1v = (col + 1 < Nreal) ? bias[col + 1] : 0.f;
            float v00 = acc[mt][nt][0] + b0v;
            float v01 = acc[mt][nt][1] + b1v;
            float v10 = acc[mt][nt][2] + b0v;
            float v11 = acc[mt][nt][3] + b1v;
            if (RELU){
                v00 = fmaxf(v00, 0.f); v01 = fmaxf(v01, 0.f);
                v10 = fmaxf(v10, 0.f); v11 = fmaxf(v11, 0.f);
            }
            if (CVT){
                v00 = __uint_as_float(cvt_tf32(v00)); v01 = __uint_as_float(cvt_tf32(v01));
                v10 = __uint_as_float(cvt_tf32(v10)); v11 = __uint_as_float(cvt_tf32(v11));
            }
            C[(size_t)row * Nstore + col]           = v00;
            C[(size_t)row * Nstore + col + 1]       = v01;
            C[(size_t)(row + 8) * Nstore + col]     = v10;
            C[(size_t)(row + 8) * Nstore + col + 1] = v11;
        }
    }
}

__global__ void zbar_kernel()
{
    const int b = blockIdx.x;
    for (int j = threadIdx.x; j < kN2; j += blockDim.x){
        float s = 0.f;
        for (int t = 0; t < kT; t++) s += g_z2[((size_t)b * kT + t) * kNP2 + j];
        g_zbar[b * kN2 + j] = s * (1.f / (float)kT);
    }
}

__global__ void logits_kernel(const float* __restrict__ w2, const float* __restrict__ b2, float* __restrict__ out)
{
    __shared__ float red[8];
    const int b = blockIdx.x >> 1, o = blockIdx.x & 1;
    float s = 0.f;
    for (int j = threadIdx.x; j < kN2; j += 256)
        s += g_zbar[b * kN2 + j] * w2[o * kN2 + j];
#pragma unroll
    for (int off = 16; off; off >>= 1) s += __shfl_xor_sync(0xffffffffu, s, off);
    if ((threadIdx.x & 31) == 0) red[threadIdx.x >> 5] = s;
    __syncthreads();
    if (threadIdx.x == 0){
        float t = 0.f;
        for (int i = 0; i < 8; i++) t += red[i];
        out[b * 2 + o] = t + b2[o];
    }
}

__global__ void xcopy_kernel(const float* __restrict__ x, float* __restrict__ outx)
{
    const int n = kB * (kT - 1) * kC;
    for (int idx = blockIdx.x * blockDim.x + threadIdx.x; idx < n; idx += gridDim.x * blockDim.x){
        int b = idx / ((kT - 1) * kC);
        int r = idx - b * (kT - 1) * kC;
        outx[idx] = x[(size_t)b * kT * kC + kC + r];
    }
}

extern "C" void kernel_launch(void* const* d_in, const int* in_sizes, int n_in,
                              void* d_out, int out_size)
{
    const float* x        = (const float*)d_in[0];
    const float* w_emb    = (const float*)d_in[1];
    const float* b_emb    = (const float*)d_in[2];
    const float* w_ih     = (const float*)d_in[3];
    const float* w_hh     = (const float*)d_in[4];
    const float* b_ih     = (const float*)d_in[5];
    const float* b_hh     = (const float*)d_in[6];
    const float* q_w0     = (const float*)d_in[7];
    const float* q_b0     = (const float*)d_in[8];
    const float* q_w1     = (const float*)d_in[9];
    const float* q_b1     = (const float*)d_in[10];
    const float* q_w2     = (const float*)d_in[11];
    const float* q_b2     = (const float*)d_in[12];
    const float* k_w0     = (const float*)d_in[13];
    const float* k_b0     = (const float*)d_in[14];
    const float* k_w1     = (const float*)d_in[15];
    const float* k_b1     = (const float*)d_in[16];
    const float* k_w2     = (const float*)d_in[17];
    const float* k_b2     = (const float*)d_in[18];
    const float* gate_bias= (const float*)d_in[19];
    const float* pred_w   = (const float*)d_in[20];
    const float* pred_b   = (const float*)d_in[21];
    const float* clf_w0   = (const float*)d_in[22];
    const float* clf_b0   = (const float*)d_in[23];
    const float* clf_w1   = (const float*)d_in[24];
    const float* clf_b1   = (const float*)d_in[25];
    const float* clf_w2   = (const float*)d_in[26];
    const float* clf_b2   = (const float*)d_in[27];

    float* out      = (float*)d_out;
    float* out_log  = out;
    float* out_fnc  = out + 2 * kB;
    float* out_mix  = out_fnc + (size_t)kB * kC2;
    float* out_pred = out_mix + (size_t)kB * kT * kC2;
    float* out_x    = out_pred + (size_t)kB * (kT - 1) * kC;

    const int smem_gemm = 3 * 2 * 4608 * 4;   // 110,592 B
    cudaFuncSetAttribute(recurrent_kernel, cudaFuncAttributeMaxDynamicSharedMemorySize, SM_BYTES);
    cudaFuncSetAttribute(mma_gemm<true, true>,  cudaFuncAttributeMaxDynamicSharedMemorySize, smem_gemm);
    cudaFuncSetAttribute(mma_gemm<true, false>, cudaFuncAttributeMaxDynamicSharedMemorySize, smem_gemm);

    prep_small<<<48, 256>>>(w_ih, w_emb, b_emb, b_ih, w_hh);
    prep_frag<<<32, 256>>>(q_w0, q_w1, q_w2, k_w0, k_w1, k_w2);
    pack_clf<<<2048, 256>>>(clf_w0, clf_w1);

    recurrent_kernel<<<2 * kB, kTH, SM_BYTES>>>(x, b_hh, q_b0, q_b1, q_b2, k_b0, k_b1, k_b2,
                                                gate_bias, pred_w, pred_b,
                                                out_mix, out_fnc, out_pred);

    float *pz1, *pz2, *pw0p, *pw1p, *pmixp;
    cudaGetSymbolAddress((void**)&pz1,   g_z1);
    cudaGetSymbolAddress((void**)&pz2,   g_z2);
    cudaGetSymbolAddress((void**)&pw0p,  g_w0p);
    cudaGetSymbolAddress((void**)&pw1p,  g_w1p);
    cudaGetSymbolAddress((void**)&pmixp, g_mixp);

    mma_gemm<true, true ><<<dim3(kNP1 / 128, kM / 128), 256, smem_gemm>>>(pmixp, pw0p, clf_b0, pz1, kM, kNP1, kN1, kKP0);
    mma_gemm<true, false><<<dim3(kNP2 / 128, kM / 128), 256, smem_gemm>>>(pz1,   pw1p, clf_b1, pz2, kM, kNP2, kN2, kNP1);

    zbar_kernel<<<kB, 256>>>();
    logits_kernel<<<2 * kB, 256>>>(clf_w2, clf_b2, out_log);
    xcopy_kernel<<<512, 256>>>(x, out_x);
}